// round 12
// baseline (speedup 1.0000x reference)
#include <cuda_runtime.h>
#include <cuda_fp16.h>
#include <cstdint>

// Problem constants
#define B_      32
#define NTOK    3136
#define DIMC    768
#define DIM3    2304
#define HEADS   12
#define HD      64
#define NW      49
#define WS      16
#define TPW     64
#define MTOK    784
#define KDIM    768

#define NELEM_X   ((size_t)B_ * NTOK * DIMC)
#define NELEM_O   ((size_t)B_ * MTOK * DIMC)
#define WQT_ELEMS ((size_t)DIM3 * DIMC)
#define WPT_ELEMS ((size_t)DIMC * DIMC)

// Scratch (device globals: allocation-free rule)
__device__ __half g_qkv[(size_t)B_ * NTOK * DIM3];   // fp16 qkv
__device__ __half g_xh[NELEM_X];
__device__ __half g_oh[NELEM_O];
__device__ __half g_wt[WQT_ELEMS + WPT_ELEMS];       // [N][K] transposed, fp16

// ---------------------------------------------------------------------------
// PTX helpers
// ---------------------------------------------------------------------------
__device__ __forceinline__ uint32_t smem_u32(const void* p) {
    uint32_t a;
    asm("{ .reg .u64 t; cvta.to.shared.u64 t, %1; cvt.u32.u64 %0, t; }" : "=r"(a) : "l"(p));
    return a;
}
#define CP_ASYNC16(dst, src) \
    asm volatile("cp.async.cg.shared.global [%0], [%1], 16;" :: "r"(dst), "l"(src))
#define CP_COMMIT() asm volatile("cp.async.commit_group;" ::: "memory")
#define CP_WAIT2()  asm volatile("cp.async.wait_group 2;" ::: "memory")

#define LDSM4(r, addr) \
    asm volatile("ldmatrix.sync.aligned.m8n8.x4.shared.b16 {%0,%1,%2,%3}, [%4];" \
                 : "=r"((r)[0]), "=r"((r)[1]), "=r"((r)[2]), "=r"((r)[3]) : "r"(addr))
#define LDSM4T(r, addr) \
    asm volatile("ldmatrix.sync.aligned.m8n8.x4.trans.shared.b16 {%0,%1,%2,%3}, [%4];" \
                 : "=r"((r)[0]), "=r"((r)[1]), "=r"((r)[2]), "=r"((r)[3]) : "r"(addr))

#define MMA_F16(c, a, b0, b1) \
    asm volatile("mma.sync.aligned.m16n8k16.row.col.f32.f16.f16.f32 " \
                 "{%0,%1,%2,%3}, {%4,%5,%6,%7}, {%8,%9}, {%0,%1,%2,%3};" \
                 : "+f"((c)[0]), "+f"((c)[1]), "+f"((c)[2]), "+f"((c)[3]) \
                 : "r"((a)[0]), "r"((a)[1]), "r"((a)[2]), "r"((a)[3]), \
                   "r"(b0), "r"(b1))

// ---------------------------------------------------------------------------
// fp16 GEMM: tile 128x128, 8 warps (warp tile 32x64), KC=64, 1 CTA/SM.
// 4-stage cp.async ring (prefetch distance 3) + explicit fragment
// double-buffering (LDSMs of j+1 issue under MMAs of j) — breaks the
// LDSM/MMA phase-lock that capped tensor busy at ~61%.
// SMEM: 64-fp16 rows (128B), 16B chunk g at (g ^ (r&7)) — conflict-free.
// ---------------------------------------------------------------------------
#define TILE_MN   128
#define KC        64
#define MAT_BYTES 16384
#define STG_BYTES 32768
#define NSTAGE    4
#define GEMM_SMEM (NSTAGE * STG_BYTES)  // 131072

__device__ __forceinline__ void load_stage(
    const __half* __restrict__ A, const __half* __restrict__ Bt,
    int m0, int n0, int kt, int K, uint32_t buf, int tid)
{
    #pragma unroll
    for (int i = 0; i < 8; ++i) {
        int idx = tid + i * 256;
        int mat = idx >> 10;
        int c   = idx & 1023;
        int r   = c >> 3;
        int g   = c & 7;
        const __half* src = (mat ? Bt : A)
                          + (size_t)((mat ? n0 : m0) + r) * K + kt + g * 8;
        uint32_t dst = buf + mat * MAT_BYTES + r * 128 + ((g ^ (r & 7)) * 16);
        CP_ASYNC16(dst, src);
    }
    CP_COMMIT();
}

template <int OUT_HALF>
__global__ __launch_bounds__(256, 1)
void gemm_f16_kernel(const __half* __restrict__ A, const __half* __restrict__ Bt,
                     const float* __restrict__ bias, void* __restrict__ Cv,
                     int M, int N, int K)
{
    extern __shared__ char smem[];
    const uint32_t sb = smem_u32(smem);
    const int tid = threadIdx.x, wid = tid >> 5, lane = tid & 31;
    const int wm = wid & 3, wn = wid >> 2;
    const int m0 = blockIdx.y * TILE_MN;
    const int n0 = blockIdx.x * TILE_MN;

    float acc[2][8][4];
    #pragma unroll
    for (int mt = 0; mt < 2; ++mt)
        #pragma unroll
        for (int nt = 0; nt < 8; ++nt)
            #pragma unroll
            for (int j = 0; j < 4; ++j) acc[mt][nt][j] = 0.f;

    const int NST = K / KC;               // 12
    load_stage(A, Bt, m0, n0, 0,      K, sb,                 tid);
    load_stage(A, Bt, m0, n0, KC,     K, sb + STG_BYTES,     tid);
    load_stage(A, Bt, m0, n0, 2 * KC, K, sb + 2 * STG_BYTES, tid);

    // per-lane ldmatrix geometry
    const int a_row  = wm * 32 + (lane & 15);
    const int a_csel = lane >> 4;
    const int a_sx   = a_row & 7;
    const uint32_t a_base = (uint32_t)a_row * 128;
    const int b_row  = wn * 64 + (lane & 7) + ((lane & 16) ? 8 : 0);
    const int b_csel = (lane >> 3) & 1;
    const int b_sx   = b_row & 7;
    const uint32_t b_base = MAT_BYTES + (uint32_t)b_row * 128;

    uint32_t af[2][2][4], bf[2][4][4];    // double-buffered fragments

    for (int s = 0; s < NST; ++s) {
        const uint32_t buf = sb + (uint32_t)(s & 3) * STG_BYTES;
        CP_WAIT2();                        // stage-s data landed
        __syncthreads();                   // stage s-1 reads all done
        if (s + 3 < NST)
            load_stage(A, Bt, m0, n0, (s + 3) * KC, K,
                       sb + (uint32_t)((s + 3) & 3) * STG_BYTES, tid);
        else
            CP_COMMIT();                   // keep group accounting aligned

        // prime j=0 fragments into slot 0
        {
            const uint32_t a_co = ((a_csel) ^ a_sx) * 16;
            const uint32_t b_co = ((b_csel) ^ b_sx) * 16;
            #pragma unroll
            for (int mt = 0; mt < 2; ++mt)
                LDSM4(af[0][mt], buf + a_base + mt * (16 * 128) + a_co);
            #pragma unroll
            for (int p = 0; p < 4; ++p)
                LDSM4(bf[0][p], buf + b_base + p * (16 * 128) + b_co);
        }
        #pragma unroll
        for (int j = 0; j < 4; ++j) {
            const int cur = j & 1, nxt = cur ^ 1;
            if (j < 3) {                   // prefetch j+1 under MMAs of j
                const uint32_t a_co = ((2 * (j + 1) + a_csel) ^ a_sx) * 16;
                const uint32_t b_co = ((2 * (j + 1) + b_csel) ^ b_sx) * 16;
                #pragma unroll
                for (int mt = 0; mt < 2; ++mt)
                    LDSM4(af[nxt][mt], buf + a_base + mt * (16 * 128) + a_co);
                #pragma unroll
                for (int p = 0; p < 4; ++p)
                    LDSM4(bf[nxt][p], buf + b_base + p * (16 * 128) + b_co);
            }
            #pragma unroll
            for (int p = 0; p < 4; ++p)
                #pragma unroll
                for (int mt = 0; mt < 2; ++mt) {
                    MMA_F16(acc[mt][2 * p],     af[cur][mt], bf[cur][p][0], bf[cur][p][1]);
                    MMA_F16(acc[mt][2 * p + 1], af[cur][mt], bf[cur][p][2], bf[cur][p][3]);
                }
        }
    }

    // Epilogue: registers -> gmem with bias
    #pragma unroll
    for (int nt = 0; nt < 8; ++nt) {
        const int col = n0 + wn * 64 + nt * 8 + (lane & 3) * 2;
        const float2 bi = *(const float2*)&bias[col];
        #pragma unroll
        for (int mt = 0; mt < 2; ++mt) {
            const int row = m0 + wm * 32 + mt * 16 + (lane >> 2);
            if (OUT_HALF) {
                __half* C = (__half*)Cv;
                *(__half2*)&C[(size_t)row * N + col] =
                    __floats2half2_rn(acc[mt][nt][0] + bi.x, acc[mt][nt][1] + bi.y);
                *(__half2*)&C[(size_t)(row + 8) * N + col] =
                    __floats2half2_rn(acc[mt][nt][2] + bi.x, acc[mt][nt][3] + bi.y);
            } else {
                float* C = (float*)Cv;
                *(float2*)&C[(size_t)row * N + col] =
                    make_float2(acc[mt][nt][0] + bi.x, acc[mt][nt][1] + bi.y);
                *(float2*)&C[(size_t)(row + 8) * N + col] =
                    make_float2(acc[mt][nt][2] + bi.x, acc[mt][nt][3] + bi.y);
            }
        }
    }
}

// ---------------------------------------------------------------------------
// x -> fp16
// ---------------------------------------------------------------------------
__global__ void xconv_kernel(const float* __restrict__ X, __half* __restrict__ H, int n4)
{
    int i = blockIdx.x * blockDim.x + threadIdx.x;
    if (i >= n4) return;
    float4 v = ((const float4*)X)[i];
    ((__half2*)H)[2 * i]     = __floats2half2_rn(v.x, v.y);
    ((__half2*)H)[2 * i + 1] = __floats2half2_rn(v.z, v.w);
}

// ---------------------------------------------------------------------------
// W[K][N] -> W^T fp16 [N][K]
// ---------------------------------------------------------------------------
__global__ void wconv_kernel(const float* __restrict__ W, __half* __restrict__ Wt,
                             int K, int N)
{
    __shared__ float t[32][33];
    const int nb = blockIdx.x * 32, kb = blockIdx.y * 32;
    const int tx = threadIdx.x, ty = threadIdx.y;
    #pragma unroll
    for (int j = 0; j < 4; ++j)
        t[ty + 8 * j][tx] = W[(size_t)(kb + ty + 8 * j) * N + nb + tx];
    __syncthreads();
    #pragma unroll
    for (int j = 0; j < 4; ++j) {
        int n = nb + ty + 8 * j, k = kb + tx;
        Wt[(size_t)n * K + k] = __float2half_rn(t[tx][ty + 8 * j]);
    }
}

// ---------------------------------------------------------------------------
// Tensor-core windowed attention (verified R11 version, unchanged).
// Block = 128 thr = one (b, w, h); cooperative gather, warp-split MMA.
// ---------------------------------------------------------------------------
__global__ __launch_bounds__(128)
void attn_kernel(const __half* __restrict__ qkv, __half* __restrict__ oh)
{
    __shared__ __half KS[TPW * 64];
    __shared__ __half VS[TPW * 64];
    __shared__ __half QP[WS * 64];
    __shared__ __half PS[WS * 64];
    __shared__ float  LG[WS][68];

    const int tid = threadIdx.x, wj = tid >> 5, lane = tid & 31;
    const int w = blockIdx.x, h = blockIdx.y, b = blockIdx.z;
    const __half* bp = qkv + (size_t)b * NTOK * DIM3 + h * HD;

    uint32_t* ks32 = (uint32_t*)KS;
    uint32_t* vs32 = (uint32_t*)VS;
    uint32_t* qp32 = (uint32_t*)QP;
    #pragma unroll
    for (int i = 0; i < 16; ++i) {
        int idx = tid + i * 128;
        int t = idx >> 5, d2 = idx & 31;
        const __half* rowp = bp + (size_t)(t * NW + w) * DIM3;
        uint32_t kv = *(const uint32_t*)(rowp + DIMC + 2 * d2);
        uint32_t vv = *(const uint32_t*)(rowp + 2 * DIMC + 2 * d2);
        int slot = t * 32 + (((d2 >> 2) ^ (t & 7)) << 2) + (d2 & 3);
        ks32[slot] = kv;
        vs32[slot] = vv;
    }
    #pragma unroll
    for (int i = 0; i < 4; ++i) {
        int idx = tid + i * 128;
        int qi = idx >> 5, d2 = idx & 31;
        uint32_t u = *(const uint32_t*)(bp + (size_t)(qi * NW + w) * DIM3 + 2 * d2);
        __half2 m = *(__half2*)&u;
        #pragma unroll
        for (int s = 1; s < 4; ++s) {
            uint32_t u2 = *(const uint32_t*)
                (bp + (size_t)((s * WS + qi) * NW + w) * DIM3 + 2 * d2);
            m = __hmax2(m, *(__half2*)&u2);
        }
        int slot = qi * 32 + (((d2 >> 2) ^ (qi & 7)) << 2) + (d2 & 3);
        qp32[slot] = *(uint32_t*)&m;
    }
    __syncthreads();

    const uint32_t KSa = smem_u32(KS), VSa = smem_u32(VS);
    const uint32_t QPa = smem_u32(QP), PSa = smem_u32(PS);

    const int aro = lane & 15, acs = lane >> 4, asx = aro & 7;
    const int r1 = lane >> 2, c0 = (lane & 3) * 2;

    {
        float sa[2][4];
        #pragma unroll
        for (int f = 0; f < 2; ++f)
            #pragma unroll
            for (int j = 0; j < 4; ++j) sa[f][j] = 0.f;
        const int bro = (lane & 7) + ((lane & 16) ? 8 : 0);
        const int bcs = (lane >> 3) & 1, bsx = bro & 7;
        #pragma unroll
        for (int k = 0; k < 4; ++k) {
            uint32_t qf[4], kf[4];
            LDSM4(qf, QPa + (uint32_t)aro * 128 + (((2 * k + acs) ^ asx) << 4));
            LDSM4(kf, KSa + (uint32_t)(wj * 16 + bro) * 128
                        + (((2 * k + bcs) ^ bsx) << 4));
            MMA_F16(sa[0], qf, kf[0], kf[1]);
            MMA_F16(sa[1], qf, kf[2], kf[3]);
        }
        #pragma unroll
        for (int f = 0; f < 2; ++f) {
            const int c = wj * 16 + f * 8 + c0;
            LG[r1][c]         = sa[f][0] * 0.125f;
            LG[r1][c + 1]     = sa[f][1] * 0.125f;
            LG[r1 + 8][c]     = sa[f][2] * 0.125f;
            LG[r1 + 8][c + 1] = sa[f][3] * 0.125f;
        }
    }
    __syncthreads();

    #pragma unroll
    for (int r = wj * 4; r < wj * 4 + 4; ++r) {
        float x0 = LG[r][lane], x1 = LG[r][lane + 32];
        float m = fmaxf(x0, x1);
        #pragma unroll
        for (int o = 16; o; o >>= 1)
            m = fmaxf(m, __shfl_xor_sync(0xffffffffu, m, o));
        float e0 = __expf(x0 - m), e1 = __expf(x1 - m);
        float s = e0 + e1;
        #pragma unroll
        for (int o = 16; o; o >>= 1)
            s += __shfl_xor_sync(0xffffffffu, s, o);
        float inv = 1.f / s;
        PS[r * 64 + ((((lane >> 3))     ^ (r & 7)) << 3) + (lane & 7)] =
            __float2half_rn(e0 * inv);
        PS[r * 64 + ((((lane >> 3) + 4) ^ (r & 7)) << 3) + (lane & 7)] =
            __float2half_rn(e1 * inv);
    }
    __syncthreads();

    {
        float oa[2][4];
        #pragma unroll
        for (int f = 0; f < 2; ++f)
            #pragma unroll
            for (int j = 0; j < 4; ++j) oa[f][j] = 0.f;
        const int vro = (lane & 7) + ((lane & 8) ? 8 : 0);
        const int vcs = (lane >> 4) & 1, vsx = vro & 7;
        #pragma unroll
        for (int i = 0; i < 4; ++i) {
            uint32_t pf[4], vf[4];
            LDSM4(pf, PSa + (uint32_t)aro * 128 + (((2 * i + acs) ^ asx) << 4));
            LDSM4T(vf, VSa + (uint32_t)(i * 16 + vro) * 128
                         + (((2 * wj + vcs) ^ vsx) << 4));
            MMA_F16(oa[0], pf, vf[0], vf[1]);
            MMA_F16(oa[1], pf, vf[2], vf[3]);
        }
        const size_t ob = (size_t)b * MTOK * DIMC + h * HD;
        const size_t tok1 = (size_t)(r1 * NW + w) * DIMC;
        const size_t tok2 = (size_t)((r1 + 8) * NW + w) * DIMC;
        #pragma unroll
        for (int f = 0; f < 2; ++f) {
            const int d = wj * 16 + f * 8 + c0;
            *(__half2*)&oh[ob + tok1 + d] = __floats2half2_rn(oa[f][0], oa[f][1]);
            *(__half2*)&oh[ob + tok2 + d] = __floats2half2_rn(oa[f][2], oa[f][3]);
        }
    }
}

// ---------------------------------------------------------------------------
extern "C" void kernel_launch(void* const* d_in, const int* in_sizes, int n_in,
                              void* d_out, int out_size)
{
    const float* x     = (const float*)d_in[0];
    const float* Wqkv  = (const float*)d_in[1];
    const float* bqkv  = (const float*)d_in[2];
    const float* Wproj = (const float*)d_in[3];
    const float* bproj = (const float*)d_in[4];
    float* out = (float*)d_out;

    __half *qkvp, *xh, *oh, *wt;
    cudaGetSymbolAddress((void**)&qkvp, g_qkv);
    cudaGetSymbolAddress((void**)&xh, g_xh);
    cudaGetSymbolAddress((void**)&oh, g_oh);
    cudaGetSymbolAddress((void**)&wt, g_wt);

    cudaFuncSetAttribute(gemm_f16_kernel<0>,
                         cudaFuncAttributeMaxDynamicSharedMemorySize, GEMM_SMEM);
    cudaFuncSetAttribute(gemm_f16_kernel<1>,
                         cudaFuncAttributeMaxDynamicSharedMemorySize, GEMM_SMEM);

    // 0a) x -> fp16
    {
        int n4 = (int)(NELEM_X / 4);
        xconv_kernel<<<n4 / 256, 256>>>(x, xh, n4);
    }
    // 0b) transpose weights -> fp16 [N][K]
    {
        dim3 bdim(32, 8);
        wconv_kernel<<<dim3(DIM3 / 32, DIMC / 32), bdim>>>(Wqkv, wt, DIMC, DIM3);
        wconv_kernel<<<dim3(DIMC / 32, DIMC / 32), bdim>>>(Wproj, wt + WQT_ELEMS,
                                                           DIMC, DIMC);
    }
    // 1) QKV projection -> fp16 qkv
    {
        dim3 grid(DIM3 / TILE_MN, (B_ * NTOK) / TILE_MN);   // (18, 784)
        gemm_f16_kernel<1><<<grid, 256, GEMM_SMEM>>>(xh, wt, bqkv, qkvp,
                                                     B_ * NTOK, DIM3, KDIM);
    }
    // 2) tensor-core windowed attention with query max-pool
    {
        dim3 grid(NW, HEADS, B_);                           // (49, 12, 32)
        attn_kernel<<<grid, 128>>>(qkvp, oh);
    }
    // 3) output projection -> fp32 out
    {
        dim3 grid(DIMC / TILE_MN, (B_ * MTOK) / TILE_MN);   // (6, 196)
        gemm_f16_kernel<0><<<grid, 256, GEMM_SMEM>>>(oh, wt + WQT_ELEMS,
                                                     bproj, out, B_ * MTOK, DIMC, KDIM);
    }
}

// round 13
// speedup vs baseline: 1.1472x; 1.1472x over previous
#include <cuda_runtime.h>
#include <cuda_fp16.h>
#include <cstdint>

// Problem constants
#define B_      32
#define NTOK    3136
#define DIMC    768
#define DIM3    2304
#define HEADS   12
#define HD      64
#define NW      49
#define WS      16
#define TPW     64
#define MTOK    784
#define KDIM    768

#define NELEM_X   ((size_t)B_ * NTOK * DIMC)
#define NELEM_O   ((size_t)B_ * MTOK * DIMC)
#define WQT_ELEMS ((size_t)DIM3 * DIMC)
#define WPT_ELEMS ((size_t)DIMC * DIMC)

// Scratch (device globals: allocation-free rule)
__device__ __half g_qkv[(size_t)B_ * NTOK * DIM3];   // fp16 qkv, token-permuted
__device__ __half g_xh[NELEM_X];
__device__ __half g_oh[NELEM_O];
__device__ __half g_wt[WQT_ELEMS + WPT_ELEMS];       // [N][K] transposed, fp16

// ---------------------------------------------------------------------------
// PTX helpers
// ---------------------------------------------------------------------------
__device__ __forceinline__ uint32_t smem_u32(const void* p) {
    uint32_t a;
    asm("{ .reg .u64 t; cvta.to.shared.u64 t, %1; cvt.u32.u64 %0, t; }" : "=r"(a) : "l"(p));
    return a;
}
#define CP_ASYNC16(dst, src) \
    asm volatile("cp.async.cg.shared.global [%0], [%1], 16;" :: "r"(dst), "l"(src))
#define CP_COMMIT() asm volatile("cp.async.commit_group;" ::: "memory")
#define CP_WAIT1()  asm volatile("cp.async.wait_group 1;" ::: "memory")

#define LDSM4(r, addr) \
    asm volatile("ldmatrix.sync.aligned.m8n8.x4.shared.b16 {%0,%1,%2,%3}, [%4];" \
                 : "=r"((r)[0]), "=r"((r)[1]), "=r"((r)[2]), "=r"((r)[3]) : "r"(addr))
#define LDSM4T(r, addr) \
    asm volatile("ldmatrix.sync.aligned.m8n8.x4.trans.shared.b16 {%0,%1,%2,%3}, [%4];" \
                 : "=r"((r)[0]), "=r"((r)[1]), "=r"((r)[2]), "=r"((r)[3]) : "r"(addr))

#define MMA_F16(c, a, b0, b1) \
    asm volatile("mma.sync.aligned.m16n8k16.row.col.f32.f16.f16.f32 " \
                 "{%0,%1,%2,%3}, {%4,%5,%6,%7}, {%8,%9}, {%0,%1,%2,%3};" \
                 : "+f"((c)[0]), "+f"((c)[1]), "+f"((c)[2]), "+f"((c)[3]) \
                 : "r"((a)[0]), "r"((a)[1]), "r"((a)[2]), "r"((a)[3]), \
                   "r"(b0), "r"(b1))

// ---------------------------------------------------------------------------
// fp16 GEMM (R11 config — empirical optimum: 128 regs, 2 CTA/SM).
// Tile 128x128, 8 warps (warp tile 32x64), KC=64, 3-stage cp.async ring.
// QPERM=1: output row (b, n) remapped to n' = (n%49)*64 + n/49 so window
// tokens become contiguous for the attention gather (zero epilogue cost:
// stores stay 128B-coalesced per row, only the row base changes).
// ---------------------------------------------------------------------------
#define TILE_MN   128
#define KC        64
#define MAT_BYTES 16384
#define STG_BYTES 32768
#define NSTAGE    3
#define GEMM_SMEM (NSTAGE * STG_BYTES)  // 98304

__device__ __forceinline__ size_t qperm_row(int row) {
    int b = row / NTOK;
    int n = row - b * NTOK;
    int t = n / NW;
    int w = n - t * NW;
    return (size_t)b * NTOK + (size_t)(w * TPW + t);
}

__device__ __forceinline__ void load_stage(
    const __half* __restrict__ A, const __half* __restrict__ Bt,
    int m0, int n0, int kt, int K, uint32_t buf, int tid)
{
    #pragma unroll
    for (int i = 0; i < 8; ++i) {
        int idx = tid + i * 256;
        int mat = idx >> 10;
        int c   = idx & 1023;
        int r   = c >> 3;
        int g   = c & 7;
        const __half* src = (mat ? Bt : A)
                          + (size_t)((mat ? n0 : m0) + r) * K + kt + g * 8;
        uint32_t dst = buf + mat * MAT_BYTES + r * 128 + ((g ^ (r & 7)) * 16);
        CP_ASYNC16(dst, src);
    }
    CP_COMMIT();
}

template <int OUT_HALF, int QPERM>
__global__ __launch_bounds__(256, 2)
void gemm_f16_kernel(const __half* __restrict__ A, const __half* __restrict__ Bt,
                     const float* __restrict__ bias, void* __restrict__ Cv,
                     int M, int N, int K)
{
    extern __shared__ char smem[];
    const uint32_t sb = smem_u32(smem);
    const int tid = threadIdx.x, wid = tid >> 5, lane = tid & 31;
    const int wm = wid & 3, wn = wid >> 2;
    const int m0 = blockIdx.y * TILE_MN;
    const int n0 = blockIdx.x * TILE_MN;

    float acc[2][8][4];
    #pragma unroll
    for (int mt = 0; mt < 2; ++mt)
        #pragma unroll
        for (int nt = 0; nt < 8; ++nt)
            #pragma unroll
            for (int j = 0; j < 4; ++j) acc[mt][nt][j] = 0.f;

    const int NST = K / KC;
    load_stage(A, Bt, m0, n0, 0,  K, sb,             tid);
    load_stage(A, Bt, m0, n0, KC, K, sb + STG_BYTES, tid);

    const int a_row  = wm * 32 + (lane & 15);
    const int a_csel = lane >> 4;
    const int a_sx   = a_row & 7;
    const uint32_t a_base = (uint32_t)a_row * 128;
    const int b_row  = wn * 64 + (lane & 7) + ((lane & 16) ? 8 : 0);
    const int b_csel = (lane >> 3) & 1;
    const int b_sx   = b_row & 7;
    const uint32_t b_base = MAT_BYTES + (uint32_t)b_row * 128;

    for (int s = 0; s < NST; ++s) {
        const uint32_t buf = sb + (uint32_t)(s % NSTAGE) * STG_BYTES;
        CP_WAIT1();
        __syncthreads();
        if (s + 2 < NST)
            load_stage(A, Bt, m0, n0, (s + 2) * KC, K,
                       sb + (uint32_t)((s + 2) % NSTAGE) * STG_BYTES, tid);
        else
            CP_COMMIT();

        #pragma unroll
        for (int j = 0; j < 4; ++j) {
            uint32_t af[2][4], bf[4][4];
            const uint32_t a_co = ((2 * j + a_csel) ^ a_sx) * 16;
            const uint32_t b_co = ((2 * j + b_csel) ^ b_sx) * 16;
            #pragma unroll
            for (int mt = 0; mt < 2; ++mt)
                LDSM4(af[mt], buf + a_base + mt * (16 * 128) + a_co);
            #pragma unroll
            for (int p = 0; p < 4; ++p)
                LDSM4(bf[p], buf + b_base + p * (16 * 128) + b_co);
            #pragma unroll
            for (int p = 0; p < 4; ++p)
                #pragma unroll
                for (int mt = 0; mt < 2; ++mt) {
                    MMA_F16(acc[mt][2 * p],     af[mt], bf[p][0], bf[p][1]);
                    MMA_F16(acc[mt][2 * p + 1], af[mt], bf[p][2], bf[p][3]);
                }
        }
    }

    // Epilogue: registers -> gmem with bias (rows remapped if QPERM)
    size_t rbase[2][2];
    #pragma unroll
    for (int mt = 0; mt < 2; ++mt) {
        const int row = m0 + wm * 32 + mt * 16 + (lane >> 2);
        rbase[mt][0] = QPERM ? qperm_row(row)     : (size_t)row;
        rbase[mt][1] = QPERM ? qperm_row(row + 8) : (size_t)(row + 8);
    }
    #pragma unroll
    for (int nt = 0; nt < 8; ++nt) {
        const int col = n0 + wn * 64 + nt * 8 + (lane & 3) * 2;
        const float2 bi = *(const float2*)&bias[col];
        #pragma unroll
        for (int mt = 0; mt < 2; ++mt) {
            if (OUT_HALF) {
                __half* C = (__half*)Cv;
                *(__half2*)&C[rbase[mt][0] * N + col] =
                    __floats2half2_rn(acc[mt][nt][0] + bi.x, acc[mt][nt][1] + bi.y);
                *(__half2*)&C[rbase[mt][1] * N + col] =
                    __floats2half2_rn(acc[mt][nt][2] + bi.x, acc[mt][nt][3] + bi.y);
            } else {
                float* C = (float*)Cv;
                *(float2*)&C[rbase[mt][0] * N + col] =
                    make_float2(acc[mt][nt][0] + bi.x, acc[mt][nt][1] + bi.y);
                *(float2*)&C[rbase[mt][1] * N + col] =
                    make_float2(acc[mt][nt][2] + bi.x, acc[mt][nt][3] + bi.y);
            }
        }
    }
}

// ---------------------------------------------------------------------------
// x -> fp16
// ---------------------------------------------------------------------------
__global__ void xconv_kernel(const float* __restrict__ X, __half* __restrict__ H, int n4)
{
    int i = blockIdx.x * blockDim.x + threadIdx.x;
    if (i >= n4) return;
    float4 v = ((const float4*)X)[i];
    ((__half2*)H)[2 * i]     = __floats2half2_rn(v.x, v.y);
    ((__half2*)H)[2 * i + 1] = __floats2half2_rn(v.z, v.w);
}

// ---------------------------------------------------------------------------
// W[K][N] -> W^T fp16 [N][K]
// ---------------------------------------------------------------------------
__global__ void wconv_kernel(const float* __restrict__ W, __half* __restrict__ Wt,
                             int K, int N)
{
    __shared__ float t[32][33];
    const int nb = blockIdx.x * 32, kb = blockIdx.y * 32;
    const int tx = threadIdx.x, ty = threadIdx.y;
    #pragma unroll
    for (int j = 0; j < 4; ++j)
        t[ty + 8 * j][tx] = W[(size_t)(kb + ty + 8 * j) * N + nb + tx];
    __syncthreads();
    #pragma unroll
    for (int j = 0; j < 4; ++j) {
        int n = nb + ty + 8 * j, k = kb + tx;
        Wt[(size_t)n * K + k] = __float2half_rn(t[tx][ty + 8 * j]);
    }
}

// ---------------------------------------------------------------------------
// Tensor-core windowed attention (verified R11 MMA plumbing).
// qkv is token-PERMUTED: row for (b, w, t) = b*NTOK + w*64 + t, so the
// whole window is one contiguous ~294KB region (4.6KB t-stride).
// Block = 128 thr = one (b, w, h); cooperative gather, warp-split MMA.
// ---------------------------------------------------------------------------
__global__ __launch_bounds__(128)
void attn_kernel(const __half* __restrict__ qkv, __half* __restrict__ oh)
{
    __shared__ __half KS[TPW * 64];
    __shared__ __half VS[TPW * 64];
    __shared__ __half QP[WS * 64];
    __shared__ __half PS[WS * 64];
    __shared__ float  LG[WS][68];

    const int tid = threadIdx.x, wj = tid >> 5, lane = tid & 31;
    const int w = blockIdx.x, h = blockIdx.y, b = blockIdx.z;
    // permuted base: token t of window w lives at row b*NTOK + w*64 + t
    const __half* bp = qkv + ((size_t)b * NTOK + (size_t)w * TPW) * DIM3 + h * HD;

    uint32_t* ks32 = (uint32_t*)KS;
    uint32_t* vs32 = (uint32_t*)VS;
    uint32_t* qp32 = (uint32_t*)QP;
    #pragma unroll
    for (int i = 0; i < 16; ++i) {
        int idx = tid + i * 128;
        int t = idx >> 5, d2 = idx & 31;
        const __half* rowp = bp + (size_t)t * DIM3;
        uint32_t kv = *(const uint32_t*)(rowp + DIMC + 2 * d2);
        uint32_t vv = *(const uint32_t*)(rowp + 2 * DIMC + 2 * d2);
        int slot = t * 32 + (((d2 >> 2) ^ (t & 7)) << 2) + (d2 & 3);
        ks32[slot] = kv;
        vs32[slot] = vv;
    }
    #pragma unroll
    for (int i = 0; i < 4; ++i) {
        int idx = tid + i * 128;
        int qi = idx >> 5, d2 = idx & 31;
        uint32_t u = *(const uint32_t*)(bp + (size_t)qi * DIM3 + 2 * d2);
        __half2 m = *(__half2*)&u;
        #pragma unroll
        for (int s = 1; s < 4; ++s) {
            uint32_t u2 = *(const uint32_t*)
                (bp + (size_t)(s * WS + qi) * DIM3 + 2 * d2);
            m = __hmax2(m, *(__half2*)&u2);
        }
        int slot = qi * 32 + (((d2 >> 2) ^ (qi & 7)) << 2) + (d2 & 3);
        qp32[slot] = *(uint32_t*)&m;
    }
    __syncthreads();

    const uint32_t KSa = smem_u32(KS), VSa = smem_u32(VS);
    const uint32_t QPa = smem_u32(QP), PSa = smem_u32(PS);

    const int aro = lane & 15, acs = lane >> 4, asx = aro & 7;
    const int r1 = lane >> 2, c0 = (lane & 3) * 2;

    {
        float sa[2][4];
        #pragma unroll
        for (int f = 0; f < 2; ++f)
            #pragma unroll
            for (int j = 0; j < 4; ++j) sa[f][j] = 0.f;
        const int bro = (lane & 7) + ((lane & 16) ? 8 : 0);
        const int bcs = (lane >> 3) & 1, bsx = bro & 7;
        #pragma unroll
        for (int k = 0; k < 4; ++k) {
            uint32_t qf[4], kf[4];
            LDSM4(qf, QPa + (uint32_t)aro * 128 + (((2 * k + acs) ^ asx) << 4));
            LDSM4(kf, KSa + (uint32_t)(wj * 16 + bro) * 128
                        + (((2 * k + bcs) ^ bsx) << 4));
            MMA_F16(sa[0], qf, kf[0], kf[1]);
            MMA_F16(sa[1], qf, kf[2], kf[3]);
        }
        #pragma unroll
        for (int f = 0; f < 2; ++f) {
            const int c = wj * 16 + f * 8 + c0;
            LG[r1][c]         = sa[f][0] * 0.125f;
            LG[r1][c + 1]     = sa[f][1] * 0.125f;
            LG[r1 + 8][c]     = sa[f][2] * 0.125f;
            LG[r1 + 8][c + 1] = sa[f][3] * 0.125f;
        }
    }
    __syncthreads();

    #pragma unroll
    for (int r = wj * 4; r < wj * 4 + 4; ++r) {
        float x0 = LG[r][lane], x1 = LG[r][lane + 32];
        float m = fmaxf(x0, x1);
        #pragma unroll
        for (int o = 16; o; o >>= 1)
            m = fmaxf(m, __shfl_xor_sync(0xffffffffu, m, o));
        float e0 = __expf(x0 - m), e1 = __expf(x1 - m);
        float s = e0 + e1;
        #pragma unroll
        for (int o = 16; o; o >>= 1)
            s += __shfl_xor_sync(0xffffffffu, s, o);
        float inv = 1.f / s;
        PS[r * 64 + ((((lane >> 3))     ^ (r & 7)) << 3) + (lane & 7)] =
            __float2half_rn(e0 * inv);
        PS[r * 64 + ((((lane >> 3) + 4) ^ (r & 7)) << 3) + (lane & 7)] =
            __float2half_rn(e1 * inv);
    }
    __syncthreads();

    {
        float oa[2][4];
        #pragma unroll
        for (int f = 0; f < 2; ++f)
            #pragma unroll
            for (int j = 0; j < 4; ++j) oa[f][j] = 0.f;
        const int vro = (lane & 7) + ((lane & 8) ? 8 : 0);
        const int vcs = (lane >> 4) & 1, vsx = vro & 7;
        #pragma unroll
        for (int i = 0; i < 4; ++i) {
            uint32_t pf[4], vf[4];
            LDSM4(pf, PSa + (uint32_t)aro * 128 + (((2 * i + acs) ^ asx) << 4));
            LDSM4T(vf, VSa + (uint32_t)(i * 16 + vro) * 128
                         + (((2 * wj + vcs) ^ vsx) << 4));
            MMA_F16(oa[0], pf, vf[0], vf[1]);
            MMA_F16(oa[1], pf, vf[2], vf[3]);
        }
        const size_t ob = (size_t)b * MTOK * DIMC + h * HD;
        const size_t tok1 = (size_t)(r1 * NW + w) * DIMC;
        const size_t tok2 = (size_t)((r1 + 8) * NW + w) * DIMC;
        #pragma unroll
        for (int f = 0; f < 2; ++f) {
            const int d = wj * 16 + f * 8 + c0;
            *(__half2*)&oh[ob + tok1 + d] = __floats2half2_rn(oa[f][0], oa[f][1]);
            *(__half2*)&oh[ob + tok2 + d] = __floats2half2_rn(oa[f][2], oa[f][3]);
        }
    }
}

// ---------------------------------------------------------------------------
extern "C" void kernel_launch(void* const* d_in, const int* in_sizes, int n_in,
                              void* d_out, int out_size)
{
    const float* x     = (const float*)d_in[0];
    const float* Wqkv  = (const float*)d_in[1];
    const float* bqkv  = (const float*)d_in[2];
    const float* Wproj = (const float*)d_in[3];
    const float* bproj = (const float*)d_in[4];
    float* out = (float*)d_out;

    __half *qkvp, *xh, *oh, *wt;
    cudaGetSymbolAddress((void**)&qkvp, g_qkv);
    cudaGetSymbolAddress((void**)&xh, g_xh);
    cudaGetSymbolAddress((void**)&oh, g_oh);
    cudaGetSymbolAddress((void**)&wt, g_wt);

    cudaFuncSetAttribute((const void*)gemm_f16_kernel<1, 1>,
                         cudaFuncAttributeMaxDynamicSharedMemorySize, GEMM_SMEM);
    cudaFuncSetAttribute((const void*)gemm_f16_kernel<0, 0>,
                         cudaFuncAttributeMaxDynamicSharedMemorySize, GEMM_SMEM);

    // 0a) x -> fp16
    {
        int n4 = (int)(NELEM_X / 4);
        xconv_kernel<<<n4 / 256, 256>>>(x, xh, n4);
    }
    // 0b) transpose weights -> fp16 [N][K]
    {
        dim3 bdim(32, 8);
        wconv_kernel<<<dim3(DIM3 / 32, DIMC / 32), bdim>>>(Wqkv, wt, DIMC, DIM3);
        wconv_kernel<<<dim3(DIMC / 32, DIMC / 32), bdim>>>(Wproj, wt + WQT_ELEMS,
                                                           DIMC, DIMC);
    }
    // 1) QKV projection -> fp16 qkv (token-permuted for gather locality)
    {
        dim3 grid(DIM3 / TILE_MN, (B_ * NTOK) / TILE_MN);   // (18, 784)
        gemm_f16_kernel<1, 1><<<grid, 256, GEMM_SMEM>>>(xh, wt, bqkv, qkvp,
                                                        B_ * NTOK, DIM3, KDIM);
    }
    // 2) tensor-core windowed attention with query max-pool
    {
        dim3 grid(NW, HEADS, B_);                           // (49, 12, 32)
        attn_kernel<<<grid, 128>>>(qkvp, oh);
    }
    // 3) output projection -> fp32 out
    {
        dim3 grid(DIMC / TILE_MN, (B_ * MTOK) / TILE_MN);   // (6, 196)
        gemm_f16_kernel<0, 0><<<grid, 256, GEMM_SMEM>>>(oh, wt + WQT_ELEMS,
                                                        bproj, out, B_ * MTOK, DIMC, KDIM);
    }
}

// round 15
// speedup vs baseline: 1.1934x; 1.0403x over previous
#include <cuda_runtime.h>
#include <cuda_fp16.h>
#include <cstdint>

// Problem constants
#define B_      32
#define NTOK    3136
#define DIMC    768
#define DIM3    2304
#define HEADS   12
#define HD      64
#define NW      49
#define WS      16
#define TPW     64
#define MTOK    784
#define KDIM    768

#define NELEM_X   ((size_t)B_ * NTOK * DIMC)
#define NELEM_O   ((size_t)B_ * MTOK * DIMC)
#define WQT_ELEMS ((size_t)DIM3 * DIMC)
#define WPT_ELEMS ((size_t)DIMC * DIMC)

// Scratch (device globals: allocation-free rule)
__device__ __half g_qkv[(size_t)B_ * NTOK * DIM3];   // fp16 k/v, window-contiguous rows
__device__ __half g_qp[(size_t)B_ * MTOK * DIMC];    // pooled q [b][w][qi][768]
__device__ __half g_xh[NELEM_X];                     // fp16 x, PERMUTED rows (w*64+t)
__device__ __half g_oh[NELEM_O];
__device__ __half g_wt[WQT_ELEMS + WPT_ELEMS];       // [N][K] transposed, fp16

// ---------------------------------------------------------------------------
// PTX helpers
// ---------------------------------------------------------------------------
__device__ __forceinline__ uint32_t smem_u32(const void* p) {
    uint32_t a;
    asm("{ .reg .u64 t; cvta.to.shared.u64 t, %1; cvt.u32.u64 %0, t; }" : "=r"(a) : "l"(p));
    return a;
}
#define CP_ASYNC16(dst, src) \
    asm volatile("cp.async.cg.shared.global [%0], [%1], 16;" :: "r"(dst), "l"(src))
#define CP_COMMIT() asm volatile("cp.async.commit_group;" ::: "memory")
#define CP_WAIT1()  asm volatile("cp.async.wait_group 1;" ::: "memory")

#define LDSM4(r, addr) \
    asm volatile("ldmatrix.sync.aligned.m8n8.x4.shared.b16 {%0,%1,%2,%3}, [%4];" \
                 : "=r"((r)[0]), "=r"((r)[1]), "=r"((r)[2]), "=r"((r)[3]) : "r"(addr))
#define LDSM4T(r, addr) \
    asm volatile("ldmatrix.sync.aligned.m8n8.x4.trans.shared.b16 {%0,%1,%2,%3}, [%4];" \
                 : "=r"((r)[0]), "=r"((r)[1]), "=r"((r)[2]), "=r"((r)[3]) : "r"(addr))

#define MMA_F16(c, a, b0, b1) \
    asm volatile("mma.sync.aligned.m16n8k16.row.col.f32.f16.f16.f32 " \
                 "{%0,%1,%2,%3}, {%4,%5,%6,%7}, {%8,%9}, {%0,%1,%2,%3};" \
                 : "+f"((c)[0]), "+f"((c)[1]), "+f"((c)[2]), "+f"((c)[3]) \
                 : "r"((a)[0]), "r"((a)[1]), "r"((a)[2]), "r"((a)[3]), \
                   "r"(b0), "r"(b1))

// ---------------------------------------------------------------------------
// fp16 GEMM (128 regs, 2 CTA/SM — empirical optimum).
// Tile 128x128, 8 warps (warp tile 32x64), KC=64, 3-stage cp.async ring.
// QPOOL=1 (QKV): A rows are ALREADY window-contiguous (permuted in xconv),
//   so each 128-row tile = exactly 2 complete windows.
//   q tiles (n0 < 768): epilogue max-pools in-CTA -> g_qp only.
//   k/v tiles: identity store (rows already permuted).
// ---------------------------------------------------------------------------
#define TILE_MN   128
#define KC        64
#define MAT_BYTES 16384
#define STG_BYTES 32768
#define NSTAGE    3
#define GEMM_SMEM (NSTAGE * STG_BYTES)  // 98304
#define QB_STR    136                   // fp16 row stride of epilogue bounce

__device__ __forceinline__ void load_stage(
    const __half* __restrict__ A, const __half* __restrict__ Bt,
    int m0, int n0, int kt, int K, uint32_t buf, int tid)
{
    #pragma unroll
    for (int i = 0; i < 8; ++i) {
        int idx = tid + i * 256;
        int mat = idx >> 10;
        int c   = idx & 1023;
        int r   = c >> 3;
        int g   = c & 7;
        const __half* src = (mat ? Bt : A)
                          + (size_t)((mat ? n0 : m0) + r) * K + kt + g * 8;
        uint32_t dst = buf + mat * MAT_BYTES + r * 128 + ((g ^ (r & 7)) * 16);
        CP_ASYNC16(dst, src);
    }
    CP_COMMIT();
}

template <int OUT_HALF, int QPOOL>
__global__ __launch_bounds__(256, 2)
void gemm_f16_kernel(const __half* __restrict__ A, const __half* __restrict__ Bt,
                     const float* __restrict__ bias, void* __restrict__ Cv,
                     __half* __restrict__ qpool,
                     int M, int N, int K)
{
    extern __shared__ char smem[];
    const uint32_t sb = smem_u32(smem);
    const int tid = threadIdx.x, wid = tid >> 5, lane = tid & 31;
    const int wm = wid & 3, wn = wid >> 2;
    const int m0 = blockIdx.y * TILE_MN;
    const int n0 = blockIdx.x * TILE_MN;

    float acc[2][8][4];
    #pragma unroll
    for (int mt = 0; mt < 2; ++mt)
        #pragma unroll
        for (int nt = 0; nt < 8; ++nt)
            #pragma unroll
            for (int j = 0; j < 4; ++j) acc[mt][nt][j] = 0.f;

    const int NST = K / KC;
    load_stage(A, Bt, m0, n0, 0,  K, sb,             tid);
    load_stage(A, Bt, m0, n0, KC, K, sb + STG_BYTES, tid);

    const int a_row  = wm * 32 + (lane & 15);
    const int a_csel = lane >> 4;
    const int a_sx   = a_row & 7;
    const uint32_t a_base = (uint32_t)a_row * 128;
    const int b_row  = wn * 64 + (lane & 7) + ((lane & 16) ? 8 : 0);
    const int b_csel = (lane >> 3) & 1;
    const int b_sx   = b_row & 7;
    const uint32_t b_base = MAT_BYTES + (uint32_t)b_row * 128;

    for (int s = 0; s < NST; ++s) {
        const uint32_t buf = sb + (uint32_t)(s % NSTAGE) * STG_BYTES;
        CP_WAIT1();
        __syncthreads();
        if (s + 2 < NST)
            load_stage(A, Bt, m0, n0, (s + 2) * KC, K,
                       sb + (uint32_t)((s + 2) % NSTAGE) * STG_BYTES, tid);
        else
            CP_COMMIT();

        #pragma unroll
        for (int j = 0; j < 4; ++j) {
            uint32_t af[2][4], bf[4][4];
            const uint32_t a_co = ((2 * j + a_csel) ^ a_sx) * 16;
            const uint32_t b_co = ((2 * j + b_csel) ^ b_sx) * 16;
            #pragma unroll
            for (int mt = 0; mt < 2; ++mt)
                LDSM4(af[mt], buf + a_base + mt * (16 * 128) + a_co);
            #pragma unroll
            for (int p = 0; p < 4; ++p)
                LDSM4(bf[p], buf + b_base + p * (16 * 128) + b_co);
            #pragma unroll
            for (int p = 0; p < 4; ++p)
                #pragma unroll
                for (int mt = 0; mt < 2; ++mt) {
                    MMA_F16(acc[mt][2 * p],     af[mt], bf[p][0], bf[p][1]);
                    MMA_F16(acc[mt][2 * p + 1], af[mt], bf[p][2], bf[p][3]);
                }
        }
    }

    if (QPOOL && n0 < DIMC) {
        // ---- q tile: rows are 2 complete windows; pool in-CTA ----
        __syncthreads();                  // stage reads done; reuse SMEM
        __half* QB = (__half*)smem;       // [128][QB_STR]
        #pragma unroll
        for (int nt = 0; nt < 8; ++nt) {
            const int col = wn * 64 + nt * 8 + (lane & 3) * 2;
            const float2 bi = *(const float2*)&bias[n0 + col];
            #pragma unroll
            for (int mt = 0; mt < 2; ++mt) {
                const int row = wm * 32 + mt * 16 + (lane >> 2);
                *(__half2*)&QB[row * QB_STR + col] =
                    __floats2half2_rn(acc[mt][nt][0] + bi.x, acc[mt][nt][1] + bi.y);
                *(__half2*)&QB[(row + 8) * QB_STR + col] =
                    __floats2half2_rn(acc[mt][nt][2] + bi.x, acc[mt][nt][3] + bi.y);
            }
        }
        __syncthreads();
        // 2 windows x 16 qi x 64 half2-cols = 2048 slots
        #pragma unroll
        for (int i = 0; i < 8; ++i) {
            int idx = tid + i * 256;
            int u  = idx >> 10;
            int r2 = idx & 1023;
            int qi = r2 >> 6;
            int c2 = r2 & 63;
            const int rb = u * 64 + qi;   // rows u*64 + (qi + 16s) = t of window u
            __half2 m = *(__half2*)&QB[rb * QB_STR + 2 * c2];
            m = __hmax2(m, *(__half2*)&QB[(rb + 16) * QB_STR + 2 * c2]);
            m = __hmax2(m, *(__half2*)&QB[(rb + 32) * QB_STR + 2 * c2]);
            m = __hmax2(m, *(__half2*)&QB[(rb + 48) * QB_STR + 2 * c2]);
            const int g = m0 / TPW + u;   // = b*49 + w (rows are permuted)
            const int b = g / NW, w = g - b * NW;
            *(__half2*)&qpool[((size_t)(b * MTOK + w * WS + qi)) * DIMC
                              + n0 + 2 * c2] = m;
        }
        return;
    }

    // ---- normal epilogue (k/v tiles: identity rows; proj GEMM) ----
    #pragma unroll
    for (int nt = 0; nt < 8; ++nt) {
        const int col = n0 + wn * 64 + nt * 8 + (lane & 3) * 2;
        const float2 bi = *(const float2*)&bias[col];
        #pragma unroll
        for (int mt = 0; mt < 2; ++mt) {
            const int row = m0 + wm * 32 + mt * 16 + (lane >> 2);
            if (OUT_HALF) {
                __half* C = (__half*)Cv;
                *(__half2*)&C[(size_t)row * N + col] =
                    __floats2half2_rn(acc[mt][nt][0] + bi.x, acc[mt][nt][1] + bi.y);
                *(__half2*)&C[(size_t)(row + 8) * N + col] =
                    __floats2half2_rn(acc[mt][nt][2] + bi.x, acc[mt][nt][3] + bi.y);
            } else {
                float* C = (float*)Cv;
                *(float2*)&C[(size_t)row * N + col] =
                    make_float2(acc[mt][nt][0] + bi.x, acc[mt][nt][1] + bi.y);
                *(float2*)&C[(size_t)(row + 8) * N + col] =
                    make_float2(acc[mt][nt][2] + bi.x, acc[mt][nt][3] + bi.y);
            }
        }
    }
}

// ---------------------------------------------------------------------------
// x -> fp16, PERMUTED rows: original token n = t*49 + w of batch b goes to
// row b*NTOK + w*64 + t. Row payload (768 ch) stays contiguous -> coalesced.
// ---------------------------------------------------------------------------
__global__ void xconv_kernel(const float* __restrict__ X, __half* __restrict__ H, int n4)
{
    int i = blockIdx.x * blockDim.x + threadIdx.x;
    if (i >= n4) return;
    const int row = i / (DIMC / 4);
    const int c4  = i - row * (DIMC / 4);
    const int b = row / NTOK;
    const int n = row - b * NTOK;
    const int t = n / NW;
    const int w = n - t * NW;
    const size_t drow = (size_t)b * NTOK + (size_t)(w * TPW + t);
    float4 v = ((const float4*)X)[i];
    __half2* dst = (__half2*)(H + drow * DIMC + c4 * 4);
    dst[0] = __floats2half2_rn(v.x, v.y);
    dst[1] = __floats2half2_rn(v.z, v.w);
}

// ---------------------------------------------------------------------------
// W[K][N] -> W^T fp16 [N][K]
// ---------------------------------------------------------------------------
__global__ void wconv_kernel(const float* __restrict__ W, __half* __restrict__ Wt,
                             int K, int N)
{
    __shared__ float t[32][33];
    const int nb = blockIdx.x * 32, kb = blockIdx.y * 32;
    const int tx = threadIdx.x, ty = threadIdx.y;
    #pragma unroll
    for (int j = 0; j < 4; ++j)
        t[ty + 8 * j][tx] = W[(size_t)(kb + ty + 8 * j) * N + nb + tx];
    __syncthreads();
    #pragma unroll
    for (int j = 0; j < 4; ++j) {
        int n = nb + ty + 8 * j, k = kb + tx;
        Wt[(size_t)n * K + k] = __float2half_rn(t[tx][ty + 8 * j]);
    }
}

// ---------------------------------------------------------------------------
// Tensor-core windowed attention. qkv rows window-contiguous; q pre-pooled.
// Block = 128 thr = one (b, w, h).
// ---------------------------------------------------------------------------
__global__ __launch_bounds__(128)
void attn_kernel(const __half* __restrict__ qkv, const __half* __restrict__ qpool,
                 __half* __restrict__ oh)
{
    __shared__ __half KS[TPW * 64];
    __shared__ __half VS[TPW * 64];
    __shared__ __half QP[WS * 64];
    __shared__ __half PS[WS * 64];
    __shared__ float  LG[WS][68];

    const int tid = threadIdx.x, wj = tid >> 5, lane = tid & 31;
    const int w = blockIdx.x, h = blockIdx.y, b = blockIdx.z;
    const __half* bp = qkv + ((size_t)b * NTOK + (size_t)w * TPW) * DIM3 + h * HD;

    uint32_t* ks32 = (uint32_t*)KS;
    uint32_t* vs32 = (uint32_t*)VS;
    uint32_t* qp32 = (uint32_t*)QP;
    #pragma unroll
    for (int i = 0; i < 16; ++i) {
        int idx = tid + i * 128;
        int t = idx >> 5, d2 = idx & 31;
        const __half* rowp = bp + (size_t)t * DIM3;
        uint32_t kv = *(const uint32_t*)(rowp + DIMC + 2 * d2);
        uint32_t vv = *(const uint32_t*)(rowp + 2 * DIMC + 2 * d2);
        int slot = t * 32 + (((d2 >> 2) ^ (t & 7)) << 2) + (d2 & 3);
        ks32[slot] = kv;
        vs32[slot] = vv;
    }
    // pre-pooled Q: contiguous 16 rows x 64 ch
    #pragma unroll
    for (int i = 0; i < 4; ++i) {
        int idx = tid + i * 128;
        int qi = idx >> 5, d2 = idx & 31;
        uint32_t u = *(const uint32_t*)
            (qpool + ((size_t)(b * MTOK + w * WS + qi)) * DIMC + h * HD + 2 * d2);
        int slot = qi * 32 + (((d2 >> 2) ^ (qi & 7)) << 2) + (d2 & 3);
        qp32[slot] = u;
    }
    __syncthreads();

    const uint32_t KSa = smem_u32(KS), VSa = smem_u32(VS);
    const uint32_t QPa = smem_u32(QP), PSa = smem_u32(PS);

    const int aro = lane & 15, acs = lane >> 4, asx = aro & 7;
    const int r1 = lane >> 2, c0 = (lane & 3) * 2;

    {
        float sa[2][4];
        #pragma unroll
        for (int f = 0; f < 2; ++f)
            #pragma unroll
            for (int j = 0; j < 4; ++j) sa[f][j] = 0.f;
        const int bro = (lane & 7) + ((lane & 16) ? 8 : 0);
        const int bcs = (lane >> 3) & 1, bsx = bro & 7;
        #pragma unroll
        for (int k = 0; k < 4; ++k) {
            uint32_t qf[4], kf[4];
            LDSM4(qf, QPa + (uint32_t)aro * 128 + (((2 * k + acs) ^ asx) << 4));
            LDSM4(kf, KSa + (uint32_t)(wj * 16 + bro) * 128
                        + (((2 * k + bcs) ^ bsx) << 4));
            MMA_F16(sa[0], qf, kf[0], kf[1]);
            MMA_F16(sa[1], qf, kf[2], kf[3]);
        }
        #pragma unroll
        for (int f = 0; f < 2; ++f) {
            const int c = wj * 16 + f * 8 + c0;
            LG[r1][c]         = sa[f][0] * 0.125f;
            LG[r1][c + 1]     = sa[f][1] * 0.125f;
            LG[r1 + 8][c]     = sa[f][2] * 0.125f;
            LG[r1 + 8][c + 1] = sa[f][3] * 0.125f;
        }
    }
    __syncthreads();

    #pragma unroll
    for (int r = wj * 4; r < wj * 4 + 4; ++r) {
        float x0 = LG[r][lane], x1 = LG[r][lane + 32];
        float m = fmaxf(x0, x1);
        #pragma unroll
        for (int o = 16; o; o >>= 1)
            m = fmaxf(m, __shfl_xor_sync(0xffffffffu, m, o));
        float e0 = __expf(x0 - m), e1 = __expf(x1 - m);
        float s = e0 + e1;
        #pragma unroll
        for (int o = 16; o; o >>= 1)
            s += __shfl_xor_sync(0xffffffffu, s, o);
        float inv = 1.f / s;
        PS[r * 64 + ((((lane >> 3))     ^ (r & 7)) << 3) + (lane & 7)] =
            __float2half_rn(e0 * inv);
        PS[r * 64 + ((((lane >> 3) + 4) ^ (r & 7)) << 3) + (lane & 7)] =
            __float2half_rn(e1 * inv);
    }
    __syncthreads();

    {
        float oa[2][4];
        #pragma unroll
        for (int f = 0; f < 2; ++f)
            #pragma unroll
            for (int j = 0; j < 4; ++j) oa[f][j] = 0.f;
        const int vro = (lane & 7) + ((lane & 8) ? 8 : 0);
        const int vcs = (lane >> 4) & 1, vsx = vro & 7;
        #pragma unroll
        for (int i = 0; i < 4; ++i) {
            uint32_t pf[4], vf[4];
            LDSM4(pf, PSa + (uint32_t)aro * 128 + (((2 * i + acs) ^ asx) << 4));
            LDSM4T(vf, VSa + (uint32_t)(i * 16 + vro) * 128
                         + (((2 * wj + vcs) ^ vsx) << 4));
            MMA_F16(oa[0], pf, vf[0], vf[1]);
            MMA_F16(oa[1], pf, vf[2], vf[3]);
        }
        const size_t ob = (size_t)b * MTOK * DIMC + h * HD;
        const size_t tok1 = (size_t)(r1 * NW + w) * DIMC;
        const size_t tok2 = (size_t)((r1 + 8) * NW + w) * DIMC;
        #pragma unroll
        for (int f = 0; f < 2; ++f) {
            const int d = wj * 16 + f * 8 + c0;
            *(__half2*)&oh[ob + tok1 + d] = __floats2half2_rn(oa[f][0], oa[f][1]);
            *(__half2*)&oh[ob + tok2 + d] = __floats2half2_rn(oa[f][2], oa[f][3]);
        }
    }
}

// ---------------------------------------------------------------------------
extern "C" void kernel_launch(void* const* d_in, const int* in_sizes, int n_in,
                              void* d_out, int out_size)
{
    const float* x     = (const float*)d_in[0];
    const float* Wqkv  = (const float*)d_in[1];
    const float* bqkv  = (const float*)d_in[2];
    const float* Wproj = (const float*)d_in[3];
    const float* bproj = (const float*)d_in[4];
    float* out = (float*)d_out;

    __half *qkvp, *qpp, *xh, *oh, *wt;
    cudaGetSymbolAddress((void**)&qkvp, g_qkv);
    cudaGetSymbolAddress((void**)&qpp, g_qp);
    cudaGetSymbolAddress((void**)&xh, g_xh);
    cudaGetSymbolAddress((void**)&oh, g_oh);
    cudaGetSymbolAddress((void**)&wt, g_wt);

    cudaFuncSetAttribute((const void*)gemm_f16_kernel<1, 1>,
                         cudaFuncAttributeMaxDynamicSharedMemorySize, GEMM_SMEM);
    cudaFuncSetAttribute((const void*)gemm_f16_kernel<0, 0>,
                         cudaFuncAttributeMaxDynamicSharedMemorySize, GEMM_SMEM);

    // 0a) x -> fp16 (window-permuted rows)
    {
        int n4 = (int)(NELEM_X / 4);
        xconv_kernel<<<n4 / 256, 256>>>(x, xh, n4);
    }
    // 0b) transpose weights -> fp16 [N][K]
    {
        dim3 bdim(32, 8);
        wconv_kernel<<<dim3(DIM3 / 32, DIMC / 32), bdim>>>(Wqkv, wt, DIMC, DIM3);
        wconv_kernel<<<dim3(DIMC / 32, DIMC / 32), bdim>>>(Wproj, wt + WQT_ELEMS,
                                                           DIMC, DIMC);
    }
    // 1) QKV projection -> fp16 k/v (window rows) + pooled q
    {
        dim3 grid(DIM3 / TILE_MN, (B_ * NTOK) / TILE_MN);   // (18, 784)
        gemm_f16_kernel<1, 1><<<grid, 256, GEMM_SMEM>>>(xh, wt, bqkv, qkvp, qpp,
                                                        B_ * NTOK, DIM3, KDIM);
    }
    // 2) tensor-core windowed attention (q pre-pooled)
    {
        dim3 grid(NW, HEADS, B_);                           // (49, 12, 32)
        attn_kernel<<<grid, 128>>>(qkvp, qpp, oh);
    }
    // 3) output projection -> fp32 out
    {
        dim3 grid(DIMC / TILE_MN, (B_ * MTOK) / TILE_MN);   // (6, 196)
        gemm_f16_kernel<0, 0><<<grid, 256, GEMM_SMEM>>>(oh, wt + WQT_ELEMS,
                                                        bproj, out, nullptr,
                                                        B_ * MTOK, DIMC, KDIM);
    }
}

// round 16
// speedup vs baseline: 1.1980x; 1.0039x over previous
#include <cuda_runtime.h>
#include <cuda_fp16.h>
#include <cstdint>

// Problem constants
#define B_      32
#define NTOK    3136
#define DIMC    768
#define DIM3    2304
#define HEADS   12
#define HD      64
#define NW      49
#define WS      16
#define TPW     64
#define MTOK    784
#define KDIM    768

#define NELEM_X   ((size_t)B_ * NTOK * DIMC)
#define NELEM_O   ((size_t)B_ * MTOK * DIMC)
#define WQT_ELEMS ((size_t)DIM3 * DIMC)
#define WPT_ELEMS ((size_t)DIMC * DIMC)

// Scratch (device globals: allocation-free rule)
__device__ __half g_qkv[(size_t)B_ * NTOK * DIM3];   // fp16 k/v, window-contiguous rows
__device__ __half g_qp[(size_t)B_ * MTOK * DIMC];    // pooled q [b][w][qi][768]
__device__ __half g_xh[NELEM_X];                     // fp16 x, PERMUTED rows (w*64+t)
__device__ __half g_oh[NELEM_O];                     // attn out, PERMUTED rows (w*16+qi)
__device__ __half g_wt[WQT_ELEMS + WPT_ELEMS];       // [N][K] transposed, fp16

// ---------------------------------------------------------------------------
// PTX helpers
// ---------------------------------------------------------------------------
__device__ __forceinline__ uint32_t smem_u32(const void* p) {
    uint32_t a;
    asm("{ .reg .u64 t; cvta.to.shared.u64 t, %1; cvt.u32.u64 %0, t; }" : "=r"(a) : "l"(p));
    return a;
}
#define CP_ASYNC16(dst, src) \
    asm volatile("cp.async.cg.shared.global [%0], [%1], 16;" :: "r"(dst), "l"(src))
#define CP_COMMIT() asm volatile("cp.async.commit_group;" ::: "memory")
#define CP_WAIT1()  asm volatile("cp.async.wait_group 1;" ::: "memory")

#define LDSM4(r, addr) \
    asm volatile("ldmatrix.sync.aligned.m8n8.x4.shared.b16 {%0,%1,%2,%3}, [%4];" \
                 : "=r"((r)[0]), "=r"((r)[1]), "=r"((r)[2]), "=r"((r)[3]) : "r"(addr))
#define LDSM4T(r, addr) \
    asm volatile("ldmatrix.sync.aligned.m8n8.x4.trans.shared.b16 {%0,%1,%2,%3}, [%4];" \
                 : "=r"((r)[0]), "=r"((r)[1]), "=r"((r)[2]), "=r"((r)[3]) : "r"(addr))

#define MMA_F16(c, a, b0, b1) \
    asm volatile("mma.sync.aligned.m16n8k16.row.col.f32.f16.f16.f32 " \
                 "{%0,%1,%2,%3}, {%4,%5,%6,%7}, {%8,%9}, {%0,%1,%2,%3};" \
                 : "+f"((c)[0]), "+f"((c)[1]), "+f"((c)[2]), "+f"((c)[3]) \
                 : "r"((a)[0]), "r"((a)[1]), "r"((a)[2]), "r"((a)[3]), \
                   "r"(b0), "r"(b1))

// ---------------------------------------------------------------------------
// fp16 GEMM (128 regs, 2 CTA/SM — empirical optimum).
// Tile 128x128, 8 warps (warp tile 32x64), KC=64, 3-stage cp.async ring.
// MODE 0: plain epilogue.
// MODE 1 (QKV): A rows window-contiguous; q tiles (n0 < 768) max-pool in-CTA
//               -> g_qp; k/v tiles identity store.
// MODE 2 (proj): A rows window-permuted; epilogue un-permutes rows
//               (row b*784 + w*16 + qi -> token m = qi*49 + w).
// ---------------------------------------------------------------------------
#define TILE_MN   128
#define KC        64
#define MAT_BYTES 16384
#define STG_BYTES 32768
#define NSTAGE    3
#define GEMM_SMEM (NSTAGE * STG_BYTES)  // 98304
#define QB_STR    136                   // fp16 row stride of epilogue bounce

__device__ __forceinline__ void load_stage(
    const __half* __restrict__ A, const __half* __restrict__ Bt,
    int m0, int n0, int kt, int K, uint32_t buf, int tid)
{
    #pragma unroll
    for (int i = 0; i < 8; ++i) {
        int idx = tid + i * 256;
        int mat = idx >> 10;
        int c   = idx & 1023;
        int r   = c >> 3;
        int g   = c & 7;
        const __half* src = (mat ? Bt : A)
                          + (size_t)((mat ? n0 : m0) + r) * K + kt + g * 8;
        uint32_t dst = buf + mat * MAT_BYTES + r * 128 + ((g ^ (r & 7)) * 16);
        CP_ASYNC16(dst, src);
    }
    CP_COMMIT();
}

template <int OUT_HALF, int MODE>
__global__ __launch_bounds__(256, 2)
void gemm_f16_kernel(const __half* __restrict__ A, const __half* __restrict__ Bt,
                     const float* __restrict__ bias, void* __restrict__ Cv,
                     __half* __restrict__ qpool,
                     int M, int N, int K)
{
    extern __shared__ char smem[];
    const uint32_t sb = smem_u32(smem);
    const int tid = threadIdx.x, wid = tid >> 5, lane = tid & 31;
    const int wm = wid & 3, wn = wid >> 2;
    const int m0 = blockIdx.y * TILE_MN;
    const int n0 = blockIdx.x * TILE_MN;

    float acc[2][8][4];
    #pragma unroll
    for (int mt = 0; mt < 2; ++mt)
        #pragma unroll
        for (int nt = 0; nt < 8; ++nt)
            #pragma unroll
            for (int j = 0; j < 4; ++j) acc[mt][nt][j] = 0.f;

    const int NST = K / KC;
    load_stage(A, Bt, m0, n0, 0,  K, sb,             tid);
    load_stage(A, Bt, m0, n0, KC, K, sb + STG_BYTES, tid);

    const int a_row  = wm * 32 + (lane & 15);
    const int a_csel = lane >> 4;
    const int a_sx   = a_row & 7;
    const uint32_t a_base = (uint32_t)a_row * 128;
    const int b_row  = wn * 64 + (lane & 7) + ((lane & 16) ? 8 : 0);
    const int b_csel = (lane >> 3) & 1;
    const int b_sx   = b_row & 7;
    const uint32_t b_base = MAT_BYTES + (uint32_t)b_row * 128;

    for (int s = 0; s < NST; ++s) {
        const uint32_t buf = sb + (uint32_t)(s % NSTAGE) * STG_BYTES;
        CP_WAIT1();
        __syncthreads();
        if (s + 2 < NST)
            load_stage(A, Bt, m0, n0, (s + 2) * KC, K,
                       sb + (uint32_t)((s + 2) % NSTAGE) * STG_BYTES, tid);
        else
            CP_COMMIT();

        #pragma unroll
        for (int j = 0; j < 4; ++j) {
            uint32_t af[2][4], bf[4][4];
            const uint32_t a_co = ((2 * j + a_csel) ^ a_sx) * 16;
            const uint32_t b_co = ((2 * j + b_csel) ^ b_sx) * 16;
            #pragma unroll
            for (int mt = 0; mt < 2; ++mt)
                LDSM4(af[mt], buf + a_base + mt * (16 * 128) + a_co);
            #pragma unroll
            for (int p = 0; p < 4; ++p)
                LDSM4(bf[p], buf + b_base + p * (16 * 128) + b_co);
            #pragma unroll
            for (int p = 0; p < 4; ++p)
                #pragma unroll
                for (int mt = 0; mt < 2; ++mt) {
                    MMA_F16(acc[mt][2 * p],     af[mt], bf[p][0], bf[p][1]);
                    MMA_F16(acc[mt][2 * p + 1], af[mt], bf[p][2], bf[p][3]);
                }
        }
    }

    if (MODE == 1 && n0 < DIMC) {
        // ---- q tile: rows are 2 complete windows; pool in-CTA ----
        __syncthreads();                  // stage reads done; reuse SMEM
        __half* QB = (__half*)smem;       // [128][QB_STR]
        #pragma unroll
        for (int nt = 0; nt < 8; ++nt) {
            const int col = wn * 64 + nt * 8 + (lane & 3) * 2;
            const float2 bi = *(const float2*)&bias[n0 + col];
            #pragma unroll
            for (int mt = 0; mt < 2; ++mt) {
                const int row = wm * 32 + mt * 16 + (lane >> 2);
                *(__half2*)&QB[row * QB_STR + col] =
                    __floats2half2_rn(acc[mt][nt][0] + bi.x, acc[mt][nt][1] + bi.y);
                *(__half2*)&QB[(row + 8) * QB_STR + col] =
                    __floats2half2_rn(acc[mt][nt][2] + bi.x, acc[mt][nt][3] + bi.y);
            }
        }
        __syncthreads();
        #pragma unroll
        for (int i = 0; i < 8; ++i) {
            int idx = tid + i * 256;
            int u  = idx >> 10;
            int r2 = idx & 1023;
            int qi = r2 >> 6;
            int c2 = r2 & 63;
            const int rb = u * 64 + qi;
            __half2 m = *(__half2*)&QB[rb * QB_STR + 2 * c2];
            m = __hmax2(m, *(__half2*)&QB[(rb + 16) * QB_STR + 2 * c2]);
            m = __hmax2(m, *(__half2*)&QB[(rb + 32) * QB_STR + 2 * c2]);
            m = __hmax2(m, *(__half2*)&QB[(rb + 48) * QB_STR + 2 * c2]);
            const int g = m0 / TPW + u;
            const int b = g / NW, w = g - b * NW;
            *(__half2*)&qpool[((size_t)(b * MTOK + w * WS + qi)) * DIMC
                              + n0 + 2 * c2] = m;
        }
        return;
    }

    // ---- normal epilogue (MODE 0/2; MODE 1 k/v tiles) ----
    #pragma unroll
    for (int nt = 0; nt < 8; ++nt) {
        const int col = n0 + wn * 64 + nt * 8 + (lane & 3) * 2;
        const float2 bi = *(const float2*)&bias[col];
        #pragma unroll
        for (int mt = 0; mt < 2; ++mt) {
            const int row = m0 + wm * 32 + mt * 16 + (lane >> 2);
            size_t r0 = (size_t)row, r1 = (size_t)(row + 8);
            if (MODE == 2) {
                // un-permute: row b*784 + w*16 + qi -> b*784 + qi*49 + w
                int b0 = row / MTOK, rr = row - b0 * MTOK;
                int w0 = rr >> 4, q0 = rr & 15;
                r0 = (size_t)b0 * MTOK + q0 * NW + w0;
                int row1 = row + 8;
                int b1 = row1 / MTOK; rr = row1 - b1 * MTOK;
                int w1 = rr >> 4, q1 = rr & 15;
                r1 = (size_t)b1 * MTOK + q1 * NW + w1;
            }
            if (OUT_HALF) {
                __half* C = (__half*)Cv;
                *(__half2*)&C[r0 * N + col] =
                    __floats2half2_rn(acc[mt][nt][0] + bi.x, acc[mt][nt][1] + bi.y);
                *(__half2*)&C[r1 * N + col] =
                    __floats2half2_rn(acc[mt][nt][2] + bi.x, acc[mt][nt][3] + bi.y);
            } else {
                float* C = (float*)Cv;
                *(float2*)&C[r0 * N + col] =
                    make_float2(acc[mt][nt][0] + bi.x, acc[mt][nt][1] + bi.y);
                *(float2*)&C[r1 * N + col] =
                    make_float2(acc[mt][nt][2] + bi.x, acc[mt][nt][3] + bi.y);
            }
        }
    }
}

// ---------------------------------------------------------------------------
// Fused prep: x -> fp16 (window-permuted rows) + both weight transposes.
// Grid: [0, XBLKS) xconv | [XBLKS, XBLKS+1728) Wqkv | rest Wproj.
// ---------------------------------------------------------------------------
#define XBLKS ((int)(NELEM_X / 1024))       // 75264 (exact: 256 thr * 4 floats)
#define WQ_TILES ((DIM3 / 32) * (DIMC / 32))  // 1728
#define WP_TILES ((DIMC / 32) * (DIMC / 32))  // 576

__global__ void prep_kernel(const float* __restrict__ X, __half* __restrict__ H,
                            const float* __restrict__ Wq, const float* __restrict__ Wp,
                            __half* __restrict__ Wt)
{
    __shared__ float t[32][33];
    const int blk = blockIdx.x, tid = threadIdx.x;

    if (blk < XBLKS) {
        const int i = blk * 256 + tid;        // float4 index
        const int row = i / (DIMC / 4);
        const int c4  = i - row * (DIMC / 4);
        const int b = row / NTOK;
        const int n = row - b * NTOK;
        const int tt = n / NW;
        const int w = n - tt * NW;
        const size_t drow = (size_t)b * NTOK + (size_t)(w * TPW + tt);
        float4 v = ((const float4*)X)[i];
        __half2* dst = (__half2*)(H + drow * DIMC + c4 * 4);
        dst[0] = __floats2half2_rn(v.x, v.y);
        dst[1] = __floats2half2_rn(v.z, v.w);
        return;
    }
    // weight transpose tile
    const float* W;
    __half* D;
    int tile, N, K;
    if (blk < XBLKS + WQ_TILES) {
        tile = blk - XBLKS; W = Wq; D = Wt;               N = DIM3; K = DIMC;
    } else {
        tile = blk - XBLKS - WQ_TILES; W = Wp; D = Wt + WQT_ELEMS; N = DIMC; K = DIMC;
    }
    const int ntiles = N / 32;
    const int nb = (tile % ntiles) * 32, kb = (tile / ntiles) * 32;
    const int tx = tid & 31, ty = tid >> 5;
    #pragma unroll
    for (int j = 0; j < 4; ++j)
        t[ty + 8 * j][tx] = W[(size_t)(kb + ty + 8 * j) * N + nb + tx];
    __syncthreads();
    #pragma unroll
    for (int j = 0; j < 4; ++j) {
        int n = nb + ty + 8 * j, k = kb + tx;
        D[(size_t)n * K + k] = __float2half_rn(t[tx][ty + 8 * j]);
    }
}

// ---------------------------------------------------------------------------
// Tensor-core windowed attention. qkv rows window-contiguous; q pre-pooled.
// Output oh in PERMUTED layout: row = b*784 + w*16 + qi (contiguous/block).
// Block = 128 thr = one (b, w, h).
// ---------------------------------------------------------------------------
__global__ __launch_bounds__(128)
void attn_kernel(const __half* __restrict__ qkv, const __half* __restrict__ qpool,
                 __half* __restrict__ oh)
{
    __shared__ __half KS[TPW * 64];
    __shared__ __half VS[TPW * 64];
    __shared__ __half QP[WS * 64];
    __shared__ __half PS[WS * 64];
    __shared__ float  LG[WS][68];

    const int tid = threadIdx.x, wj = tid >> 5, lane = tid & 31;
    const int w = blockIdx.x, h = blockIdx.y, b = blockIdx.z;
    const __half* bp = qkv + ((size_t)b * NTOK + (size_t)w * TPW) * DIM3 + h * HD;

    uint32_t* ks32 = (uint32_t*)KS;
    uint32_t* vs32 = (uint32_t*)VS;
    uint32_t* qp32 = (uint32_t*)QP;
    #pragma unroll
    for (int i = 0; i < 16; ++i) {
        int idx = tid + i * 128;
        int t = idx >> 5, d2 = idx & 31;
        const __half* rowp = bp + (size_t)t * DIM3;
        uint32_t kv = *(const uint32_t*)(rowp + DIMC + 2 * d2);
        uint32_t vv = *(const uint32_t*)(rowp + 2 * DIMC + 2 * d2);
        int slot = t * 32 + (((d2 >> 2) ^ (t & 7)) << 2) + (d2 & 3);
        ks32[slot] = kv;
        vs32[slot] = vv;
    }
    #pragma unroll
    for (int i = 0; i < 4; ++i) {
        int idx = tid + i * 128;
        int qi = idx >> 5, d2 = idx & 31;
        uint32_t u = *(const uint32_t*)
            (qpool + ((size_t)(b * MTOK + w * WS + qi)) * DIMC + h * HD + 2 * d2);
        int slot = qi * 32 + (((d2 >> 2) ^ (qi & 7)) << 2) + (d2 & 3);
        qp32[slot] = u;
    }
    __syncthreads();

    const uint32_t KSa = smem_u32(KS), VSa = smem_u32(VS);
    const uint32_t QPa = smem_u32(QP), PSa = smem_u32(PS);

    const int aro = lane & 15, acs = lane >> 4, asx = aro & 7;
    const int r1 = lane >> 2, c0 = (lane & 3) * 2;

    {
        float sa[2][4];
        #pragma unroll
        for (int f = 0; f < 2; ++f)
            #pragma unroll
            for (int j = 0; j < 4; ++j) sa[f][j] = 0.f;
        const int bro = (lane & 7) + ((lane & 16) ? 8 : 0);
        const int bcs = (lane >> 3) & 1, bsx = bro & 7;
        #pragma unroll
        for (int k = 0; k < 4; ++k) {
            uint32_t qf[4], kf[4];
            LDSM4(qf, QPa + (uint32_t)aro * 128 + (((2 * k + acs) ^ asx) << 4));
            LDSM4(kf, KSa + (uint32_t)(wj * 16 + bro) * 128
                        + (((2 * k + bcs) ^ bsx) << 4));
            MMA_F16(sa[0], qf, kf[0], kf[1]);
            MMA_F16(sa[1], qf, kf[2], kf[3]);
        }
        #pragma unroll
        for (int f = 0; f < 2; ++f) {
            const int c = wj * 16 + f * 8 + c0;
            LG[r1][c]         = sa[f][0] * 0.125f;
            LG[r1][c + 1]     = sa[f][1] * 0.125f;
            LG[r1 + 8][c]     = sa[f][2] * 0.125f;
            LG[r1 + 8][c + 1] = sa[f][3] * 0.125f;
        }
    }
    __syncthreads();

    #pragma unroll
    for (int r = wj * 4; r < wj * 4 + 4; ++r) {
        float x0 = LG[r][lane], x1 = LG[r][lane + 32];
        float m = fmaxf(x0, x1);
        #pragma unroll
        for (int o = 16; o; o >>= 1)
            m = fmaxf(m, __shfl_xor_sync(0xffffffffu, m, o));
        float e0 = __expf(x0 - m), e1 = __expf(x1 - m);
        float s = e0 + e1;
        #pragma unroll
        for (int o = 16; o; o >>= 1)
            s += __shfl_xor_sync(0xffffffffu, s, o);
        float inv = 1.f / s;
        PS[r * 64 + ((((lane >> 3))     ^ (r & 7)) << 3) + (lane & 7)] =
            __float2half_rn(e0 * inv);
        PS[r * 64 + ((((lane >> 3) + 4) ^ (r & 7)) << 3) + (lane & 7)] =
            __float2half_rn(e1 * inv);
    }
    __syncthreads();

    {
        float oa[2][4];
        #pragma unroll
        for (int f = 0; f < 2; ++f)
            #pragma unroll
            for (int j = 0; j < 4; ++j) oa[f][j] = 0.f;
        const int vro = (lane & 7) + ((lane & 8) ? 8 : 0);
        const int vcs = (lane >> 4) & 1, vsx = vro & 7;
        #pragma unroll
        for (int i = 0; i < 4; ++i) {
            uint32_t pf[4], vf[4];
            LDSM4(pf, PSa + (uint32_t)aro * 128 + (((2 * i + acs) ^ asx) << 4));
            LDSM4T(vf, VSa + (uint32_t)(i * 16 + vro) * 128
                         + (((2 * wj + vcs) ^ vsx) << 4));
            MMA_F16(oa[0], pf, vf[0], vf[1]);
            MMA_F16(oa[1], pf, vf[2], vf[3]);
        }
        // permuted store: row = b*784 + w*16 + qi
        const size_t ob = ((size_t)b * MTOK + (size_t)w * WS) * DIMC + h * HD;
        #pragma unroll
        for (int f = 0; f < 2; ++f) {
            const int d = wj * 16 + f * 8 + c0;
            *(__half2*)&oh[ob + (size_t)r1 * DIMC + d] =
                __floats2half2_rn(oa[f][0], oa[f][1]);
            *(__half2*)&oh[ob + (size_t)(r1 + 8) * DIMC + d] =
                __floats2half2_rn(oa[f][2], oa[f][3]);
        }
    }
}

// ---------------------------------------------------------------------------
extern "C" void kernel_launch(void* const* d_in, const int* in_sizes, int n_in,
                              void* d_out, int out_size)
{
    const float* x     = (const float*)d_in[0];
    const float* Wqkv  = (const float*)d_in[1];
    const float* bqkv  = (const float*)d_in[2];
    const float* Wproj = (const float*)d_in[3];
    const float* bproj = (const float*)d_in[4];
    float* out = (float*)d_out;

    __half *qkvp, *qpp, *xh, *oh, *wt;
    cudaGetSymbolAddress((void**)&qkvp, g_qkv);
    cudaGetSymbolAddress((void**)&qpp, g_qp);
    cudaGetSymbolAddress((void**)&xh, g_xh);
    cudaGetSymbolAddress((void**)&oh, g_oh);
    cudaGetSymbolAddress((void**)&wt, g_wt);

    cudaFuncSetAttribute((const void*)gemm_f16_kernel<1, 1>,
                         cudaFuncAttributeMaxDynamicSharedMemorySize, GEMM_SMEM);
    cudaFuncSetAttribute((const void*)gemm_f16_kernel<0, 2>,
                         cudaFuncAttributeMaxDynamicSharedMemorySize, GEMM_SMEM);

    // 0) fused prep: x -> fp16 (permuted) + weight transposes
    prep_kernel<<<XBLKS + WQ_TILES + WP_TILES, 256>>>(x, xh, Wqkv, Wproj, wt);

    // 1) QKV projection -> fp16 k/v (window rows) + pooled q
    {
        dim3 grid(DIM3 / TILE_MN, (B_ * NTOK) / TILE_MN);   // (18, 784)
        gemm_f16_kernel<1, 1><<<grid, 256, GEMM_SMEM>>>(xh, wt, bqkv, qkvp, qpp,
                                                        B_ * NTOK, DIM3, KDIM);
    }
    // 2) tensor-core windowed attention (q pre-pooled, permuted output)
    {
        dim3 grid(NW, HEADS, B_);                           // (49, 12, 32)
        attn_kernel<<<grid, 128>>>(qkvp, qpp, oh);
    }
    // 3) output projection -> fp32 out (epilogue un-permutes rows)
    {
        dim3 grid(DIMC / TILE_MN, (B_ * MTOK) / TILE_MN);   // (6, 196)
        gemm_f16_kernel<0, 2><<<grid, 256, GEMM_SMEM>>>(oh, wt + WQT_ELEMS,
                                                        bproj, out, nullptr,
                                                        B_ * MTOK, DIMC, KDIM);
    }
}

// round 17
// speedup vs baseline: 1.2147x; 1.0139x over previous
#include <cuda_runtime.h>
#include <cuda_fp16.h>
#include <cstdint>

// Problem constants
#define B_      32
#define NTOK    3136
#define DIMC    768
#define DIM3    2304
#define HEADS   12
#define HD      64
#define NW      49
#define WS      16
#define TPW     64
#define MTOK    784
#define KDIM    768

#define NELEM_X   ((size_t)B_ * NTOK * DIMC)
#define NELEM_O   ((size_t)B_ * MTOK * DIMC)
#define WQT_ELEMS ((size_t)DIM3 * DIMC)
#define WPT_ELEMS ((size_t)DIMC * DIMC)

// Scratch (device globals: allocation-free rule)
__device__ __half g_qkv[(size_t)B_ * NTOK * DIM3];   // fp16 k/v, window-contiguous rows
__device__ __half g_qp[(size_t)B_ * MTOK * DIMC];    // pooled q [b][w][qi][768]
__device__ __half g_xh[NELEM_X];                     // fp16 x, PERMUTED rows (w*64+t)
__device__ __half g_oh[NELEM_O];                     // attn out, PERMUTED rows (w*16+qi)
__device__ __half g_wt[WQT_ELEMS + WPT_ELEMS];       // [N][K] transposed, fp16

// ---------------------------------------------------------------------------
// PTX helpers
// ---------------------------------------------------------------------------
__device__ __forceinline__ uint32_t smem_u32(const void* p) {
    uint32_t a;
    asm("{ .reg .u64 t; cvta.to.shared.u64 t, %1; cvt.u32.u64 %0, t; }" : "=r"(a) : "l"(p));
    return a;
}
#define CP_ASYNC16(dst, src) \
    asm volatile("cp.async.cg.shared.global [%0], [%1], 16;" :: "r"(dst), "l"(src))
#define CP_COMMIT() asm volatile("cp.async.commit_group;" ::: "memory")
#define CP_WAIT1()  asm volatile("cp.async.wait_group 1;" ::: "memory")

#define LDSM4(r, addr) \
    asm volatile("ldmatrix.sync.aligned.m8n8.x4.shared.b16 {%0,%1,%2,%3}, [%4];" \
                 : "=r"((r)[0]), "=r"((r)[1]), "=r"((r)[2]), "=r"((r)[3]) : "r"(addr))
#define LDSM4T(r, addr) \
    asm volatile("ldmatrix.sync.aligned.m8n8.x4.trans.shared.b16 {%0,%1,%2,%3}, [%4];" \
                 : "=r"((r)[0]), "=r"((r)[1]), "=r"((r)[2]), "=r"((r)[3]) : "r"(addr))

#define MMA_F16(c, a, b0, b1) \
    asm volatile("mma.sync.aligned.m16n8k16.row.col.f32.f16.f16.f32 " \
                 "{%0,%1,%2,%3}, {%4,%5,%6,%7}, {%8,%9}, {%0,%1,%2,%3};" \
                 : "+f"((c)[0]), "+f"((c)[1]), "+f"((c)[2]), "+f"((c)[3]) \
                 : "r"((a)[0]), "r"((a)[1]), "r"((a)[2]), "r"((a)[3]), \
                   "r"(b0), "r"(b1))

// ---------------------------------------------------------------------------
// fp16 GEMM (128 regs, 2 CTA/SM — empirical optimum). Unchanged from R16.
// MODE 0: plain. MODE 1 (QKV): q tiles max-pool in-CTA. MODE 2 (proj):
// epilogue un-permutes rows.
// ---------------------------------------------------------------------------
#define TILE_MN   128
#define KC        64
#define MAT_BYTES 16384
#define STG_BYTES 32768
#define NSTAGE    3
#define GEMM_SMEM (NSTAGE * STG_BYTES)  // 98304
#define QB_STR    136

__device__ __forceinline__ void load_stage(
    const __half* __restrict__ A, const __half* __restrict__ Bt,
    int m0, int n0, int kt, int K, uint32_t buf, int tid)
{
    #pragma unroll
    for (int i = 0; i < 8; ++i) {
        int idx = tid + i * 256;
        int mat = idx >> 10;
        int c   = idx & 1023;
        int r   = c >> 3;
        int g   = c & 7;
        const __half* src = (mat ? Bt : A)
                          + (size_t)((mat ? n0 : m0) + r) * K + kt + g * 8;
        uint32_t dst = buf + mat * MAT_BYTES + r * 128 + ((g ^ (r & 7)) * 16);
        CP_ASYNC16(dst, src);
    }
    CP_COMMIT();
}

template <int OUT_HALF, int MODE>
__global__ __launch_bounds__(256, 2)
void gemm_f16_kernel(const __half* __restrict__ A, const __half* __restrict__ Bt,
                     const float* __restrict__ bias, void* __restrict__ Cv,
                     __half* __restrict__ qpool,
                     int M, int N, int K)
{
    extern __shared__ char smem[];
    const uint32_t sb = smem_u32(smem);
    const int tid = threadIdx.x, wid = tid >> 5, lane = tid & 31;
    const int wm = wid & 3, wn = wid >> 2;
    const int m0 = blockIdx.y * TILE_MN;
    const int n0 = blockIdx.x * TILE_MN;

    float acc[2][8][4];
    #pragma unroll
    for (int mt = 0; mt < 2; ++mt)
        #pragma unroll
        for (int nt = 0; nt < 8; ++nt)
            #pragma unroll
            for (int j = 0; j < 4; ++j) acc[mt][nt][j] = 0.f;

    const int NST = K / KC;
    load_stage(A, Bt, m0, n0, 0,  K, sb,             tid);
    load_stage(A, Bt, m0, n0, KC, K, sb + STG_BYTES, tid);

    const int a_row  = wm * 32 + (lane & 15);
    const int a_csel = lane >> 4;
    const int a_sx   = a_row & 7;
    const uint32_t a_base = (uint32_t)a_row * 128;
    const int b_row  = wn * 64 + (lane & 7) + ((lane & 16) ? 8 : 0);
    const int b_csel = (lane >> 3) & 1;
    const int b_sx   = b_row & 7;
    const uint32_t b_base = MAT_BYTES + (uint32_t)b_row * 128;

    for (int s = 0; s < NST; ++s) {
        const uint32_t buf = sb + (uint32_t)(s % NSTAGE) * STG_BYTES;
        CP_WAIT1();
        __syncthreads();
        if (s + 2 < NST)
            load_stage(A, Bt, m0, n0, (s + 2) * KC, K,
                       sb + (uint32_t)((s + 2) % NSTAGE) * STG_BYTES, tid);
        else
            CP_COMMIT();

        #pragma unroll
        for (int j = 0; j < 4; ++j) {
            uint32_t af[2][4], bf[4][4];
            const uint32_t a_co = ((2 * j + a_csel) ^ a_sx) * 16;
            const uint32_t b_co = ((2 * j + b_csel) ^ b_sx) * 16;
            #pragma unroll
            for (int mt = 0; mt < 2; ++mt)
                LDSM4(af[mt], buf + a_base + mt * (16 * 128) + a_co);
            #pragma unroll
            for (int p = 0; p < 4; ++p)
                LDSM4(bf[p], buf + b_base + p * (16 * 128) + b_co);
            #pragma unroll
            for (int p = 0; p < 4; ++p)
                #pragma unroll
                for (int mt = 0; mt < 2; ++mt) {
                    MMA_F16(acc[mt][2 * p],     af[mt], bf[p][0], bf[p][1]);
                    MMA_F16(acc[mt][2 * p + 1], af[mt], bf[p][2], bf[p][3]);
                }
        }
    }

    if (MODE == 1 && n0 < DIMC) {
        __syncthreads();
        __half* QB = (__half*)smem;       // [128][QB_STR]
        #pragma unroll
        for (int nt = 0; nt < 8; ++nt) {
            const int col = wn * 64 + nt * 8 + (lane & 3) * 2;
            const float2 bi = *(const float2*)&bias[n0 + col];
            #pragma unroll
            for (int mt = 0; mt < 2; ++mt) {
                const int row = wm * 32 + mt * 16 + (lane >> 2);
                *(__half2*)&QB[row * QB_STR + col] =
                    __floats2half2_rn(acc[mt][nt][0] + bi.x, acc[mt][nt][1] + bi.y);
                *(__half2*)&QB[(row + 8) * QB_STR + col] =
                    __floats2half2_rn(acc[mt][nt][2] + bi.x, acc[mt][nt][3] + bi.y);
            }
        }
        __syncthreads();
        #pragma unroll
        for (int i = 0; i < 8; ++i) {
            int idx = tid + i * 256;
            int u  = idx >> 10;
            int r2 = idx & 1023;
            int qi = r2 >> 6;
            int c2 = r2 & 63;
            const int rb = u * 64 + qi;
            __half2 m = *(__half2*)&QB[rb * QB_STR + 2 * c2];
            m = __hmax2(m, *(__half2*)&QB[(rb + 16) * QB_STR + 2 * c2]);
            m = __hmax2(m, *(__half2*)&QB[(rb + 32) * QB_STR + 2 * c2]);
            m = __hmax2(m, *(__half2*)&QB[(rb + 48) * QB_STR + 2 * c2]);
            const int g = m0 / TPW + u;
            const int b = g / NW, w = g - b * NW;
            *(__half2*)&qpool[((size_t)(b * MTOK + w * WS + qi)) * DIMC
                              + n0 + 2 * c2] = m;
        }
        return;
    }

    #pragma unroll
    for (int nt = 0; nt < 8; ++nt) {
        const int col = n0 + wn * 64 + nt * 8 + (lane & 3) * 2;
        const float2 bi = *(const float2*)&bias[col];
        #pragma unroll
        for (int mt = 0; mt < 2; ++mt) {
            const int row = m0 + wm * 32 + mt * 16 + (lane >> 2);
            size_t r0 = (size_t)row, r1 = (size_t)(row + 8);
            if (MODE == 2) {
                int b0 = row / MTOK, rr = row - b0 * MTOK;
                int w0 = rr >> 4, q0 = rr & 15;
                r0 = (size_t)b0 * MTOK + q0 * NW + w0;
                int row1 = row + 8;
                int b1 = row1 / MTOK; rr = row1 - b1 * MTOK;
                int w1 = rr >> 4, q1 = rr & 15;
                r1 = (size_t)b1 * MTOK + q1 * NW + w1;
            }
            if (OUT_HALF) {
                __half* C = (__half*)Cv;
                *(__half2*)&C[r0 * N + col] =
                    __floats2half2_rn(acc[mt][nt][0] + bi.x, acc[mt][nt][1] + bi.y);
                *(__half2*)&C[r1 * N + col] =
                    __floats2half2_rn(acc[mt][nt][2] + bi.x, acc[mt][nt][3] + bi.y);
            } else {
                float* C = (float*)Cv;
                *(float2*)&C[r0 * N + col] =
                    make_float2(acc[mt][nt][0] + bi.x, acc[mt][nt][1] + bi.y);
                *(float2*)&C[r1 * N + col] =
                    make_float2(acc[mt][nt][2] + bi.x, acc[mt][nt][3] + bi.y);
            }
        }
    }
}

// ---------------------------------------------------------------------------
// Fused prep (unchanged from R16)
// ---------------------------------------------------------------------------
#define XBLKS ((int)(NELEM_X / 1024))
#define WQ_TILES ((DIM3 / 32) * (DIMC / 32))
#define WP_TILES ((DIMC / 32) * (DIMC / 32))

__global__ void prep_kernel(const float* __restrict__ X, __half* __restrict__ H,
                            const float* __restrict__ Wq, const float* __restrict__ Wp,
                            __half* __restrict__ Wt)
{
    __shared__ float t[32][33];
    const int blk = blockIdx.x, tid = threadIdx.x;

    if (blk < XBLKS) {
        const int i = blk * 256 + tid;
        const int row = i / (DIMC / 4);
        const int c4  = i - row * (DIMC / 4);
        const int b = row / NTOK;
        const int n = row - b * NTOK;
        const int tt = n / NW;
        const int w = n - tt * NW;
        const size_t drow = (size_t)b * NTOK + (size_t)(w * TPW + tt);
        float4 v = ((const float4*)X)[i];
        __half2* dst = (__half2*)(H + drow * DIMC + c4 * 4);
        dst[0] = __floats2half2_rn(v.x, v.y);
        dst[1] = __floats2half2_rn(v.z, v.w);
        return;
    }
    const float* W;
    __half* D;
    int tile, N, K;
    if (blk < XBLKS + WQ_TILES) {
        tile = blk - XBLKS; W = Wq; D = Wt;               N = DIM3; K = DIMC;
    } else {
        tile = blk - XBLKS - WQ_TILES; W = Wp; D = Wt + WQT_ELEMS; N = DIMC; K = DIMC;
    }
    const int ntiles = N / 32;
    const int nb = (tile % ntiles) * 32, kb = (tile / ntiles) * 32;
    const int tx = tid & 31, ty = tid >> 5;
    #pragma unroll
    for (int j = 0; j < 4; ++j)
        t[ty + 8 * j][tx] = W[(size_t)(kb + ty + 8 * j) * N + nb + tx];
    __syncthreads();
    #pragma unroll
    for (int j = 0; j < 4; ++j) {
        int n = nb + ty + 8 * j, k = kb + tx;
        D[(size_t)n * K + k] = __float2half_rn(t[tx][ty + 8 * j]);
    }
}

// ---------------------------------------------------------------------------
// Tensor-core windowed attention, single-barrier version.
// Block = 128 thr = one (b, w, h). Cooperative gather -> ONE __syncthreads ->
// each warp: FULL 16x64 QK^T (dup 4x, trivial), in-register softmax (R10,
// verified), C-frag -> A-frag P conversion (R10, verified), P@V for its
// d-block via trans-LDSM (R11 phase-4, verified). No LG/PS SMEM.
// ---------------------------------------------------------------------------
__global__ __launch_bounds__(128)
void attn_kernel(const __half* __restrict__ qkv, const __half* __restrict__ qpool,
                 __half* __restrict__ oh)
{
    __shared__ __half KS[TPW * 64];
    __shared__ __half VS[TPW * 64];
    __shared__ __half QP[WS * 64];

    const int tid = threadIdx.x, wj = tid >> 5, lane = tid & 31;
    const int w = blockIdx.x, h = blockIdx.y, b = blockIdx.z;
    const __half* bp = qkv + ((size_t)b * NTOK + (size_t)w * TPW) * DIM3 + h * HD;

    uint32_t* ks32 = (uint32_t*)KS;
    uint32_t* vs32 = (uint32_t*)VS;
    uint32_t* qp32 = (uint32_t*)QP;
    #pragma unroll
    for (int i = 0; i < 16; ++i) {
        int idx = tid + i * 128;
        int t = idx >> 5, d2 = idx & 31;
        const __half* rowp = bp + (size_t)t * DIM3;
        uint32_t kv = *(const uint32_t*)(rowp + DIMC + 2 * d2);
        uint32_t vv = *(const uint32_t*)(rowp + 2 * DIMC + 2 * d2);
        int slot = t * 32 + (((d2 >> 2) ^ (t & 7)) << 2) + (d2 & 3);
        ks32[slot] = kv;
        vs32[slot] = vv;
    }
    #pragma unroll
    for (int i = 0; i < 4; ++i) {
        int idx = tid + i * 128;
        int qi = idx >> 5, d2 = idx & 31;
        uint32_t u = *(const uint32_t*)
            (qpool + ((size_t)(b * MTOK + w * WS + qi)) * DIMC + h * HD + 2 * d2);
        int slot = qi * 32 + (((d2 >> 2) ^ (qi & 7)) << 2) + (d2 & 3);
        qp32[slot] = u;
    }
    __syncthreads();                      // the ONLY block barrier

    const uint32_t KSa = smem_u32(KS), VSa = smem_u32(VS), QPa = smem_u32(QP);

    // ---- full logits per warp: 16 x 64, fp32 acc ----
    float sa[8][4];
    #pragma unroll
    for (int f = 0; f < 8; ++f)
        #pragma unroll
        for (int j = 0; j < 4; ++j) sa[f][j] = 0.f;

    const int aro = lane & 15, acs = lane >> 4, asx = aro & 7;
    const int bro = (lane & 7) + ((lane & 16) ? 8 : 0);
    const int bcs = (lane >> 3) & 1, bsx = bro & 7;

    #pragma unroll
    for (int k = 0; k < 4; ++k) {
        uint32_t qf[4];
        LDSM4(qf, QPa + (uint32_t)aro * 128 + (((2 * k + acs) ^ asx) << 4));
        #pragma unroll
        for (int p = 0; p < 4; ++p) {
            uint32_t kf[4];
            LDSM4(kf, KSa + (uint32_t)(p * 16 + bro) * 128
                        + (((2 * k + bcs) ^ bsx) << 4));
            MMA_F16(sa[2 * p],     qf, kf[0], kf[1]);
            MMA_F16(sa[2 * p + 1], qf, kf[2], kf[3]);
        }
    }

    // ---- in-register softmax (rows r1 = lane>>2 and r1+8) ----
    float m1 = -3.0e38f, m2 = -3.0e38f;
    #pragma unroll
    for (int f = 0; f < 8; ++f) {
        #pragma unroll
        for (int j = 0; j < 4; ++j) sa[f][j] *= 0.125f;
        m1 = fmaxf(m1, fmaxf(sa[f][0], sa[f][1]));
        m2 = fmaxf(m2, fmaxf(sa[f][2], sa[f][3]));
    }
    m1 = fmaxf(m1, __shfl_xor_sync(0xffffffffu, m1, 1));
    m1 = fmaxf(m1, __shfl_xor_sync(0xffffffffu, m1, 2));
    m2 = fmaxf(m2, __shfl_xor_sync(0xffffffffu, m2, 1));
    m2 = fmaxf(m2, __shfl_xor_sync(0xffffffffu, m2, 2));
    float s1 = 0.f, s2 = 0.f;
    #pragma unroll
    for (int f = 0; f < 8; ++f) {
        sa[f][0] = __expf(sa[f][0] - m1);
        sa[f][1] = __expf(sa[f][1] - m1);
        sa[f][2] = __expf(sa[f][2] - m2);
        sa[f][3] = __expf(sa[f][3] - m2);
        s1 += sa[f][0] + sa[f][1];
        s2 += sa[f][2] + sa[f][3];
    }
    s1 += __shfl_xor_sync(0xffffffffu, s1, 1);
    s1 += __shfl_xor_sync(0xffffffffu, s1, 2);
    s2 += __shfl_xor_sync(0xffffffffu, s2, 1);
    s2 += __shfl_xor_sync(0xffffffffu, s2, 2);
    const float i1 = 1.f / s1, i2 = 1.f / s2;

    // ---- P -> fp16 A-fragments (C-frag pairs = A-frag k8 halves) ----
    uint32_t pa[4][4];
    #pragma unroll
    for (int i = 0; i < 4; ++i) {
        const int f0 = 2 * i, f1 = 2 * i + 1;
        __half2 t0 = __floats2half2_rn(sa[f0][0] * i1, sa[f0][1] * i1);
        __half2 t1 = __floats2half2_rn(sa[f0][2] * i2, sa[f0][3] * i2);
        __half2 t2 = __floats2half2_rn(sa[f1][0] * i1, sa[f1][1] * i1);
        __half2 t3 = __floats2half2_rn(sa[f1][2] * i2, sa[f1][3] * i2);
        pa[i][0] = *(uint32_t*)&t0;
        pa[i][1] = *(uint32_t*)&t1;
        pa[i][2] = *(uint32_t*)&t2;
        pa[i][3] = *(uint32_t*)&t3;
    }

    // ---- P@V for this warp's d-block (d = 16*wj .. 16*wj+15) ----
    float oa[2][4];
    #pragma unroll
    for (int f = 0; f < 2; ++f)
        #pragma unroll
        for (int j = 0; j < 4; ++j) oa[f][j] = 0.f;
    const int vro = (lane & 7) + ((lane & 8) ? 8 : 0);
    const int vcs = (lane >> 4) & 1, vsx = vro & 7;
    #pragma unroll
    for (int i = 0; i < 4; ++i) {
        uint32_t vf[4];
        LDSM4T(vf, VSa + (uint32_t)(i * 16 + vro) * 128
                     + (((2 * wj + vcs) ^ vsx) << 4));
        MMA_F16(oa[0], pa[i], vf[0], vf[1]);
        MMA_F16(oa[1], pa[i], vf[2], vf[3]);
    }

    // ---- permuted store: row = b*784 + w*16 + qi ----
    const int r1 = lane >> 2, c0 = (lane & 3) * 2;
    const size_t ob = ((size_t)b * MTOK + (size_t)w * WS) * DIMC + h * HD;
    #pragma unroll
    for (int f = 0; f < 2; ++f) {
        const int d = wj * 16 + f * 8 + c0;
        *(__half2*)&oh[ob + (size_t)r1 * DIMC + d] =
            __floats2half2_rn(oa[f][0], oa[f][1]);
        *(__half2*)&oh[ob + (size_t)(r1 + 8) * DIMC + d] =
            __floats2half2_rn(oa[f][2], oa[f][3]);
    }
}

// ---------------------------------------------------------------------------
extern "C" void kernel_launch(void* const* d_in, const int* in_sizes, int n_in,
                              void* d_out, int out_size)
{
    const float* x     = (const float*)d_in[0];
    const float* Wqkv  = (const float*)d_in[1];
    const float* bqkv  = (const float*)d_in[2];
    const float* Wproj = (const float*)d_in[3];
    const float* bproj = (const float*)d_in[4];
    float* out = (float*)d_out;

    __half *qkvp, *qpp, *xh, *oh, *wt;
    cudaGetSymbolAddress((void**)&qkvp, g_qkv);
    cudaGetSymbolAddress((void**)&qpp, g_qp);
    cudaGetSymbolAddress((void**)&xh, g_xh);
    cudaGetSymbolAddress((void**)&oh, g_oh);
    cudaGetSymbolAddress((void**)&wt, g_wt);

    cudaFuncSetAttribute((const void*)gemm_f16_kernel<1, 1>,
                         cudaFuncAttributeMaxDynamicSharedMemorySize, GEMM_SMEM);
    cudaFuncSetAttribute((const void*)gemm_f16_kernel<0, 2>,
                         cudaFuncAttributeMaxDynamicSharedMemorySize, GEMM_SMEM);

    // 0) fused prep: x -> fp16 (permuted) + weight transposes
    prep_kernel<<<XBLKS + WQ_TILES + WP_TILES, 256>>>(x, xh, Wqkv, Wproj, wt);

    // 1) QKV projection -> fp16 k/v (window rows) + pooled q
    {
        dim3 grid(DIM3 / TILE_MN, (B_ * NTOK) / TILE_MN);   // (18, 784)
        gemm_f16_kernel<1, 1><<<grid, 256, GEMM_SMEM>>>(xh, wt, bqkv, qkvp, qpp,
                                                        B_ * NTOK, DIM3, KDIM);
    }
    // 2) tensor-core windowed attention (single-barrier, in-register softmax)
    {
        dim3 grid(NW, HEADS, B_);                           // (49, 12, 32)
        attn_kernel<<<grid, 128>>>(qkvp, qpp, oh);
    }
    // 3) output projection -> fp32 out (epilogue un-permutes rows)
    {
        dim3 grid(DIMC / TILE_MN, (B_ * MTOK) / TILE_MN);   // (6, 196)
        gemm_f16_kernel<0, 2><<<grid, 256, GEMM_SMEM>>>(oh, wt + WQT_ELEMS,
                                                        bproj, out, nullptr,
                                                        B_ * MTOK, DIMC, KDIM);
    }
}